// round 3
// baseline (speedup 1.0000x reference)
#include <cuda_runtime.h>
#include <cuda_bf16.h>
#include <cstdint>

#define N_NODES 100000
#define N_EDGES 1600000
#define IN_CH   256
#define HC      128        // HEADS*OUT_CH
#define NEG_SLOPE 0.2f

// ---------------- scratch (static device globals; no allocation) -------------
__device__ __align__(16) float g_feat[(size_t)N_NODES * HC];   // 51.2 MB
__device__ float g_esrc[N_NODES];
__device__ float g_etar[N_NODES];
__device__ float g_eself[N_NODES];
__device__ int   g_counts[N_NODES];
__device__ int   g_offsets[N_NODES];
__device__ int   g_cursor[N_NODES];
__device__ int   g_bsums[128];
__device__ int   g_srcs[N_EDGES];
__device__ float g_evals[N_EDGES];
__device__ int   g_is32;   // 1 if edge_index buffer holds int32, 0 if int64

// ---------------- Kernel 0: sniff edge_index dtype ---------------------------
__global__ void k_detect(const long long* __restrict__ p) {
    if (blockIdx.x == 0 && threadIdx.x == 0) {
        int f = 0;
        for (int j = 0; j < 64; j++) {
            long long v = p[j];
            if (v < 0 || v >= (long long)N_NODES) f = 1;
        }
        g_is32 = f;
    }
}

__device__ __forceinline__ void load_edge(const void* ei, int i, int& t, int& s) {
    if (g_is32) {
        const int* p = (const int*)ei;
        t = p[i];
        s = p[N_EDGES + i];
    } else {
        const long long* p = (const long long*)ei;
        t = (int)p[i];
        s = (int)p[N_EDGES + i];
    }
}

// ---------------- tf32 helpers -----------------------------------------------
__device__ __forceinline__ float2 split_tf32(float v) {
    uint32_t hi;
    asm("cvt.rna.tf32.f32 %0, %1;" : "=r"(hi) : "f"(v));
    float h = __uint_as_float(hi);
    float l = v - h;
    uint32_t lo;
    asm("cvt.rna.tf32.f32 %0, %1;" : "=r"(lo) : "f"(l));
    return make_float2(h, __uint_as_float(lo));
}

__device__ __forceinline__ void mma_tf32(float* d,
                                         uint32_t a0, uint32_t a1, uint32_t a2, uint32_t a3,
                                         uint32_t b0, uint32_t b1) {
    asm volatile(
        "mma.sync.aligned.m16n8k8.row.col.f32.tf32.tf32.f32 "
        "{%0,%1,%2,%3}, {%4,%5,%6,%7}, {%8,%9}, {%0,%1,%2,%3};\n"
        : "+f"(d[0]), "+f"(d[1]), "+f"(d[2]), "+f"(d[3])
        : "r"(a0), "r"(a1), "r"(a2), "r"(a3), "r"(b0), "r"(b1));
}

// ---------------- Kernel 1: GEMM feat = x @ W^T + b (3xTF32 tensor core) -----
// Block: 128 rows x 128 cols, 8 warps (warpM 0..3 -> 32 rows, warpN 0..1 -> 64 cols).
// Warp tile 32x64 = 2 m16-frags x 8 n8-frags, K chunks of 16 (2 k8 steps).
__global__ __launch_bounds__(256) void k_gemm_tc(const float* __restrict__ x,
                                                 const float* __restrict__ W,
                                                 const float* __restrict__ b) {
    __shared__ float2 xs[16][136];   // [k][m], {tf32_hi, tf32_lo}
    __shared__ float2 ws[16][136];   // [k][n]

    const int tid   = threadIdx.x;
    const int lane  = tid & 31;
    const int wid   = tid >> 5;
    const int warpM = wid & 3;
    const int warpN = wid >> 2;
    const int gid   = lane >> 2;     // groupID 0..7
    const int tig   = lane & 3;      // threadID_in_group 0..3
    const int row0  = blockIdx.x * 128;

    float acc[16][4];                // [mf*8 + j][c0..c3]
#pragma unroll
    for (int q = 0; q < 16; q++)
#pragma unroll
        for (int r = 0; r < 4; r++) acc[q][r] = 0.f;

    // prefetch registers: 2 float4 from x, 2 from W per chunk per thread
    float4 px[2], pw[2];

    // load chunk 0
#pragma unroll
    for (int l = 0; l < 2; l++) {
        int f = tid + l * 256;       // 0..511 float4 slots (128 rows x 4)
        int r = f >> 2, kq = f & 3;
        int grow = row0 + r;
        px[l] = (grow < N_NODES)
                    ? *reinterpret_cast<const float4*>(&x[(size_t)grow * IN_CH + kq * 4])
                    : make_float4(0.f, 0.f, 0.f, 0.f);
        pw[l] = *reinterpret_cast<const float4*>(&W[(size_t)r * IN_CH + kq * 4]);
    }

#pragma unroll 1
    for (int c = 0; c < 16; c++) {
        // store prefetched chunk into smem (with tf32 split)
#pragma unroll
        for (int l = 0; l < 2; l++) {
            int f = tid + l * 256;
            int r = f >> 2, kq = f & 3;
            const float* pxf = reinterpret_cast<const float*>(&px[l]);
            const float* pwf = reinterpret_cast<const float*>(&pw[l]);
#pragma unroll
            for (int i = 0; i < 4; i++) {
                xs[kq * 4 + i][r] = split_tf32(pxf[i]);
                ws[kq * 4 + i][r] = split_tf32(pwf[i]);
            }
        }
        __syncthreads();

        // issue global loads for next chunk (overlap with compute)
        if (c < 15) {
            int k0 = (c + 1) * 16;
#pragma unroll
            for (int l = 0; l < 2; l++) {
                int f = tid + l * 256;
                int r = f >> 2, kq = f & 3;
                int grow = row0 + r;
                px[l] = (grow < N_NODES)
                            ? *reinterpret_cast<const float4*>(&x[(size_t)grow * IN_CH + k0 + kq * 4])
                            : make_float4(0.f, 0.f, 0.f, 0.f);
                pw[l] = *reinterpret_cast<const float4*>(&W[(size_t)r * IN_CH + k0 + kq * 4]);
            }
        }

        // compute 2 k8-steps
#pragma unroll
        for (int ks = 0; ks < 2; ks++) {
            int kk = ks * 8;
            float2 a[2][4];
#pragma unroll
            for (int mf = 0; mf < 2; mf++) {
                int rb = warpM * 32 + mf * 16;
                a[mf][0] = xs[kk + tig][rb + gid];
                a[mf][1] = xs[kk + tig][rb + gid + 8];
                a[mf][2] = xs[kk + tig + 4][rb + gid];
                a[mf][3] = xs[kk + tig + 4][rb + gid + 8];
            }
#pragma unroll
            for (int j = 0; j < 8; j++) {
                int nb = warpN * 64 + j * 8 + gid;
                float2 b0 = ws[kk + tig][nb];
                float2 b1 = ws[kk + tig + 4][nb];
#pragma unroll
                for (int mf = 0; mf < 2; mf++) {
                    float* d = acc[mf * 8 + j];
                    uint32_t ah0 = __float_as_uint(a[mf][0].x);
                    uint32_t ah1 = __float_as_uint(a[mf][1].x);
                    uint32_t ah2 = __float_as_uint(a[mf][2].x);
                    uint32_t ah3 = __float_as_uint(a[mf][3].x);
                    uint32_t al0 = __float_as_uint(a[mf][0].y);
                    uint32_t al1 = __float_as_uint(a[mf][1].y);
                    uint32_t al2 = __float_as_uint(a[mf][2].y);
                    uint32_t al3 = __float_as_uint(a[mf][3].y);
                    uint32_t bh0 = __float_as_uint(b0.x);
                    uint32_t bh1 = __float_as_uint(b1.x);
                    uint32_t bl0 = __float_as_uint(b0.y);
                    uint32_t bl1 = __float_as_uint(b1.y);
                    mma_tf32(d, ah0, ah1, ah2, ah3, bh0, bh1);   // hi*hi
                    mma_tf32(d, ah0, ah1, ah2, ah3, bl0, bl1);   // hi*lo
                    mma_tf32(d, al0, al1, al2, al3, bh0, bh1);   // lo*hi
                }
            }
        }
        __syncthreads();
    }

    // epilogue: c0:(gid,2tig) c1:(gid,2tig+1) c2:(gid+8,2tig) c3:(gid+8,2tig+1)
#pragma unroll
    for (int mf = 0; mf < 2; mf++) {
        int r0 = row0 + warpM * 32 + mf * 16;
#pragma unroll
        for (int j = 0; j < 8; j++) {
            int cN = warpN * 64 + j * 8 + 2 * tig;
            float bx = b[cN], by = b[cN + 1];
            float* d = acc[mf * 8 + j];
            int ra = r0 + gid, rb = r0 + gid + 8;
            if (ra < N_NODES) {
                float2 o = make_float2(d[0] + bx, d[1] + by);
                *reinterpret_cast<float2*>(&g_feat[(size_t)ra * HC + cN]) = o;
            }
            if (rb < N_NODES) {
                float2 o = make_float2(d[2] + bx, d[3] + by);
                *reinterpret_cast<float2*>(&g_feat[(size_t)rb * HC + cN]) = o;
            }
        }
    }
}

// ---------------- Kernel 2: per-node attention scalars + init ----------------
__global__ __launch_bounds__(256) void k_epre(const float* __restrict__ att) {
    int warp = (blockIdx.x * blockDim.x + threadIdx.x) >> 5;
    if (warp >= N_NODES) return;
    int lane = threadIdx.x & 31;

    const float4* f4 = reinterpret_cast<const float4*>(g_feat);
    float4 f = f4[(size_t)warp * 32 + lane];
    float4 a0 = *reinterpret_cast<const float4*>(&att[lane * 8]);
    float4 a1 = *reinterpret_cast<const float4*>(&att[lane * 8 + 4]);

    float s0 = f.x * a0.x + f.y * a0.z + f.z * a1.x + f.w * a1.z;
    float s1 = f.x * a0.y + f.y * a0.w + f.z * a1.y + f.w * a1.w;
#pragma unroll
    for (int o = 16; o > 0; o >>= 1) {
        s0 += __shfl_xor_sync(0xffffffffu, s0, o);
        s1 += __shfl_xor_sync(0xffffffffu, s1, o);
    }
    if (lane == 0) {
        g_esrc[warp] = s0;
        g_etar[warp] = s1;
        float z = s0 + s1;
        float lz = z > 0.f ? z : NEG_SLOPE * z;
        g_eself[warp] = expf(lz);
        g_counts[warp] = 0;
    }
}

// ---------------- Kernel 3: histogram of destination nodes -------------------
__global__ __launch_bounds__(256) void k_hist(const void* __restrict__ ei) {
    int i = blockIdx.x * blockDim.x + threadIdx.x;
    if (i >= N_EDGES) return;
    int t, s;
    load_edge(ei, i, t, s);
    if ((unsigned)t >= N_NODES || (unsigned)s >= N_NODES) return;
    atomicAdd(&g_counts[t], 1);
}

// ---------------- Kernels 4a/4b/4c: multi-block exclusive scan ---------------
__global__ __launch_bounds__(1024) void k_scan1() {
    __shared__ int wsum[32];
    int i = blockIdx.x * 1024 + threadIdx.x;
    int lane = threadIdx.x & 31, wd = threadIdx.x >> 5;
    int v = (i < N_NODES) ? g_counts[i] : 0;
    int xv = v;
#pragma unroll
    for (int o = 1; o < 32; o <<= 1) {
        int y = __shfl_up_sync(0xffffffffu, xv, o);
        if (lane >= o) xv += y;
    }
    if (lane == 31) wsum[wd] = xv;
    __syncthreads();
    if (wd == 0) {
        int s = wsum[lane];
#pragma unroll
        for (int o = 1; o < 32; o <<= 1) {
            int y = __shfl_up_sync(0xffffffffu, s, o);
            if (lane >= o) s += y;
        }
        wsum[lane] = s;
    }
    __syncthreads();
    int base = (wd > 0) ? wsum[wd - 1] : 0;
    if (i < N_NODES) g_offsets[i] = base + xv - v;   // exclusive within block
    if (threadIdx.x == 1023) g_bsums[blockIdx.x] = wsum[31];
}

__global__ __launch_bounds__(128) void k_scan2(int nblocks) {
    __shared__ int sh[128];
    int t = threadIdx.x;
    int v = (t < nblocks) ? g_bsums[t] : 0;
    sh[t] = v;
    __syncthreads();
#pragma unroll
    for (int o = 1; o < 128; o <<= 1) {
        int y = (t >= o) ? sh[t - o] : 0;
        __syncthreads();
        sh[t] += y;
        __syncthreads();
    }
    if (t < nblocks) g_bsums[t] = sh[t] - v;   // exclusive
}

__global__ __launch_bounds__(256) void k_scan3() {
    int i = blockIdx.x * blockDim.x + threadIdx.x;
    if (i >= N_NODES) return;
    int off = g_offsets[i] + g_bsums[i >> 10];
    g_offsets[i] = off;
    g_cursor[i]  = off;
}

// ---------------- Kernel 5: scatter edges into CSR ---------------------------
__global__ __launch_bounds__(256) void k_scatter(const void* __restrict__ ei) {
    int i = blockIdx.x * blockDim.x + threadIdx.x;
    if (i >= N_EDGES) return;
    int t, s;
    load_edge(ei, i, t, s);
    if ((unsigned)t >= N_NODES || (unsigned)s >= N_NODES) return;
    float z = g_esrc[s] + g_etar[t];
    float lz = z > 0.f ? z : NEG_SLOPE * z;
    float e = expf(lz);
    int pos = atomicAdd(&g_cursor[t], 1);
    g_srcs[pos]  = s;
    g_evals[pos] = e;
}

// ---------------- Kernel 6: aggregation, one warp per node -------------------
__global__ __launch_bounds__(256) void k_agg(float* __restrict__ out) {
    int warp = (blockIdx.x * blockDim.x + threadIdx.x) >> 5;
    if (warp >= N_NODES) return;
    int lane = threadIdx.x & 31;

    const float4* f4 = reinterpret_cast<const float4*>(g_feat);
    int off = g_offsets[warp];
    int cnt = g_counts[warp];

    float4 acc = make_float4(0.f, 0.f, 0.f, 0.f);
    float sum_e = 0.f;
    int j = 0;
#pragma unroll 1
    for (; j + 4 <= cnt; j += 4) {
#pragma unroll
        for (int u = 0; u < 4; u++) {
            int s = g_srcs[off + j + u];
            float e = g_evals[off + j + u];
            sum_e += e;
            float4 f = f4[(size_t)s * 32 + lane];
            acc.x = fmaf(e, f.x, acc.x);
            acc.y = fmaf(e, f.y, acc.y);
            acc.z = fmaf(e, f.z, acc.z);
            acc.w = fmaf(e, f.w, acc.w);
        }
    }
    for (; j < cnt; j++) {
        int s = g_srcs[off + j];
        float e = g_evals[off + j];
        sum_e += e;
        float4 f = f4[(size_t)s * 32 + lane];
        acc.x = fmaf(e, f.x, acc.x);
        acc.y = fmaf(e, f.y, acc.y);
        acc.z = fmaf(e, f.z, acc.z);
        acc.w = fmaf(e, f.w, acc.w);
    }

    float es  = g_eself[warp];
    float inv = 1.0f / (sum_e + es);
    float4 fs = f4[(size_t)warp * 32 + lane];
    float4 o;
    o.x = (acc.x + es * fs.x) * inv;
    o.y = (acc.y + es * fs.y) * inv;
    o.z = (acc.z + es * fs.z) * inv;
    o.w = (acc.w + es * fs.w) * inv;
    reinterpret_cast<float4*>(out)[(size_t)warp * 32 + lane] = o;
}

// ---------------- launch ------------------------------------------------------
extern "C" void kernel_launch(void* const* d_in, const int* in_sizes, int n_in,
                              void* d_out, int out_size) {
    const float* x   = nullptr;
    const void*  ei  = nullptr;
    const float* W   = nullptr;
    const float* b   = nullptr;
    const float* att = nullptr;
    for (int i = 0; i < n_in; i++) {
        switch (in_sizes[i]) {
            case 25600000: x   = (const float*)d_in[i]; break;
            case 3200000:  ei  = d_in[i];               break;
            case 32768:    W   = (const float*)d_in[i]; break;
            case 128:      b   = (const float*)d_in[i]; break;
            case 256:      att = (const float*)d_in[i]; break;
            default: break;
        }
    }
    float* out = (float*)d_out;
    (void)out_size;

    k_detect<<<1, 32>>>((const long long*)ei);

    int gemm_blocks = (N_NODES + 127) / 128;           // 782
    k_gemm_tc<<<gemm_blocks, 256>>>(x, W, b);

    int node_warp_blocks = (N_NODES * 32 + 255) / 256; // 12500
    k_epre<<<node_warp_blocks, 256>>>(att);

    int edge_blocks = (N_EDGES + 255) / 256;           // 6250
    k_hist<<<edge_blocks, 256>>>(ei);

    int scan_blocks = (N_NODES + 1023) / 1024;         // 98
    k_scan1<<<scan_blocks, 1024>>>();
    k_scan2<<<1, 128>>>(scan_blocks);
    k_scan3<<<(N_NODES + 255) / 256, 256>>>();

    k_scatter<<<edge_blocks, 256>>>(ei);

    k_agg<<<node_warp_blocks, 256>>>(out);
}

// round 7
// speedup vs baseline: 2.0776x; 2.0776x over previous
#include <cuda_runtime.h>
#include <cuda_bf16.h>
#include <cstdint>

#define N_NODES 100000
#define N_EDGES 1600000
#define IN_CH   256
#define HC      128        // HEADS*OUT_CH
#define NEG_SLOPE 0.2f

// ---------------- scratch (static device globals; no allocation) -------------
__device__ __align__(16) float g_feat[(size_t)N_NODES * HC];   // 51.2 MB
__device__ float g_esrc[N_NODES];
__device__ float g_etar[N_NODES];
__device__ float g_eself[N_NODES];
__device__ int   g_counts[N_NODES];
__device__ int   g_offsets[N_NODES];
__device__ int   g_cursor[N_NODES];
__device__ int   g_bsums[128];
__device__ int   g_srcs[N_EDGES];
__device__ float g_evals[N_EDGES];
__device__ int   g_is32;
__device__ int   g_has_tc;   // 1 if the running SASS was built for sm_103a (tcgen05 available)

// ---------------- Kernel P: probe which fatbin variant is running ------------
__global__ void k_probe() {
#if defined(__CUDA_ARCH_FEAT_SM103_ALL)
    g_has_tc = 1;
#else
    g_has_tc = 0;
#endif
}

// ---------------- Kernel 0: sniff edge_index dtype ---------------------------
__global__ void k_detect(const long long* __restrict__ p) {
    if (blockIdx.x == 0 && threadIdx.x == 0) {
        int f = 0;
        for (int j = 0; j < 64; j++) {
            long long v = p[j];
            if (v < 0 || v >= (long long)N_NODES) f = 1;
        }
        g_is32 = f;
    }
}

__device__ __forceinline__ void load_edge(const void* ei, int i, int& t, int& s) {
    if (g_is32) {
        const int* p = (const int*)ei;
        t = p[i];
        s = p[N_EDGES + i];
    } else {
        const long long* p = (const long long*)ei;
        t = (int)p[i];
        s = (int)p[N_EDGES + i];
    }
}

// ======================= tcgen05 GEMM (sm_103a builds only) ==================
#if defined(__CUDA_ARCH_FEAT_SM103_ALL)
__device__ __forceinline__ uint32_t smem_u32(const void* p) {
    uint32_t a;
    asm("{ .reg .u64 t; cvta.to.shared.u64 t, %1; cvt.u32.u64 %0, t; }" : "=r"(a) : "l"(p));
    return a;
}
__device__ __forceinline__ uint32_t elect_one() {
    uint32_t pred;
    asm volatile("{\n\t.reg .pred p;\n\telect.sync _|p, 0xFFFFFFFF;\n\tselp.b32 %0, 1, 0, p;\n\t}"
                 : "=r"(pred));
    return pred;
}
__device__ __forceinline__ uint64_t mk_desc(uint32_t addr) {
    return ((uint64_t)2 << 61) | ((uint64_t)1 << 46) | ((uint64_t)64 << 32) |
           ((uint64_t)1 << 16) | ((uint64_t)(addr >> 4) & 0x3FFF);
}
__device__ __forceinline__ void mma_f16_ss(uint32_t d_tmem, uint64_t a_desc,
                                           uint64_t b_desc, uint32_t idesc, uint32_t en) {
    asm volatile(
        "{\n\t.reg .pred p;\n\tsetp.ne.u32 p, %5, 0;\n\t"
        "tcgen05.mma.cta_group::1.kind::f16 [%0], %1, %2, %3, {%4, %4, %4, %4}, p;\n\t}"
        :: "r"(d_tmem), "l"(a_desc), "l"(b_desc), "r"(idesc), "r"(0u), "r"(en)
        : "memory");
}
#endif

#define SWZ(x) ((x) ^ (((x) >> 3) & 0x70))
// idesc kind::f16: dtypeF32(b4) atypeBF16(b7) btypeBF16(b10) N/8<<17 M/16<<24 = 0x8200490
#define GEMM_IDESC ((1u<<4)|(1u<<7)|(1u<<10)|((HC/8)<<17)|((128/16)<<24))

#define SM_TMEMPTR 0
#define SM_MBAR    8
#define SM_A_HI    1024                  // 128 x 64 bf16 = 16KB
#define SM_A_LO    (SM_A_HI + 16384)
#define SM_W_HI    (SM_A_LO + 16384)     // 128 x 256 bf16 = 64KB
#define SM_W_LO    (SM_W_HI + 65536)
#define SM_TOTAL   (SM_W_LO + 65536)     // 164864 B

// Block tile M=128 (rows) x N=128 (all HC), K=256 in chunks of 64. bf16x3 split.
__global__ __launch_bounds__(256, 1)
void k_gemm_tc5(const float* __restrict__ x, const float* __restrict__ W,
                const float* __restrict__ b) {
#if defined(__CUDA_ARCH_FEAT_SM103_ALL)
    extern __shared__ char smem[];
    const uint32_t sbase = smem_u32(smem);
    const int tid  = threadIdx.x;
    const int wid  = tid >> 5;
    const int lane = tid & 31;
    const int row0 = blockIdx.x * 128;

    if (wid == 0) {
        asm volatile("tcgen05.alloc.cta_group::1.sync.aligned.shared::cta.b32 [%0], %1;"
                     :: "r"(sbase + SM_TMEMPTR), "r"(128u) : "memory");
    }
    if (wid == 0 && lane == 0) {
        asm volatile("mbarrier.init.shared.b64 [%0], %1;"
                     :: "r"(sbase + SM_MBAR), "r"(1u) : "memory");
    }
    __syncthreads();
    uint32_t tmem;
    asm volatile("ld.shared.b32 %0, [%1];" : "=r"(tmem) : "r"(sbase + SM_TMEMPTR));

    // W (128n x 256k) -> SW128 blocked atoms, hi/lo bf16 planes.
    for (int g = tid; g < 4096; g += 256) {
        int row = g >> 5;
        int k   = (g & 31) * 8;
        float4 v0 = *reinterpret_cast<const float4*>(&W[(size_t)row * IN_CH + k]);
        float4 v1 = *reinterpret_cast<const float4*>(&W[(size_t)row * IN_CH + k + 4]);
        float f[8] = {v0.x, v0.y, v0.z, v0.w, v1.x, v1.y, v1.z, v1.w};
        __nv_bfloat16 hb[8], lb[8];
#pragma unroll
        for (int i = 0; i < 8; i++) {
            hb[i] = __float2bfloat16_rn(f[i]);
            lb[i] = __float2bfloat16_rn(f[i] - __bfloat162float(hb[i]));
        }
        uint32_t atom = (row >> 3) + (k >> 6) * 16;
        uint32_t byte = atom * 1024 + (row & 7) * 128 + (k & 63) * 2;
        uint32_t sw = SWZ(byte);
        *reinterpret_cast<uint4*>(smem + SM_W_HI + sw) = *reinterpret_cast<uint4*>(hb);
        *reinterpret_cast<uint4*>(smem + SM_W_LO + sw) = *reinterpret_cast<uint4*>(lb);
    }

    const uint64_t a_hi_d = mk_desc(sbase + SM_A_HI);
    const uint64_t a_lo_d = mk_desc(sbase + SM_A_LO);
    const uint64_t w_hi_d = mk_desc(sbase + SM_W_HI);
    const uint64_t w_lo_d = mk_desc(sbase + SM_W_LO);

#pragma unroll 1
    for (int c = 0; c < 4; c++) {
        // A chunk: 128 rows x 64 k -> hi/lo planes (16 atoms)
        for (int g = tid; g < 1024; g += 256) {
            int row = g >> 3;
            int k   = (g & 7) * 8;
            int grow = row0 + row;
            float f[8] = {0.f, 0.f, 0.f, 0.f, 0.f, 0.f, 0.f, 0.f};
            if (grow < N_NODES) {
                float4 v0 = *reinterpret_cast<const float4*>(&x[(size_t)grow * IN_CH + c * 64 + k]);
                float4 v1 = *reinterpret_cast<const float4*>(&x[(size_t)grow * IN_CH + c * 64 + k + 4]);
                f[0]=v0.x; f[1]=v0.y; f[2]=v0.z; f[3]=v0.w;
                f[4]=v1.x; f[5]=v1.y; f[6]=v1.z; f[7]=v1.w;
            }
            __nv_bfloat16 hb[8], lb[8];
#pragma unroll
            for (int i = 0; i < 8; i++) {
                hb[i] = __float2bfloat16_rn(f[i]);
                lb[i] = __float2bfloat16_rn(f[i] - __bfloat162float(hb[i]));
            }
            uint32_t byte = (row >> 3) * 1024 + (row & 7) * 128 + k * 2;
            uint32_t sw = SWZ(byte);
            *reinterpret_cast<uint4*>(smem + SM_A_HI + sw) = *reinterpret_cast<uint4*>(hb);
            *reinterpret_cast<uint4*>(smem + SM_A_LO + sw) = *reinterpret_cast<uint4*>(lb);
        }
        asm volatile("fence.proxy.async.shared::cta;" ::: "memory");
        __syncthreads();

        if (wid == 0 && elect_one()) {
            uint64_t wbase_hi = w_hi_d + (uint64_t)c * 1024;   // 16 atoms/chunk = 1024 units
            uint64_t wbase_lo = w_lo_d + (uint64_t)c * 1024;
#pragma unroll
            for (int ks = 0; ks < 4; ks++) {                    // K=16 per mma
                uint64_t ah = a_hi_d + ks * 2;
                uint64_t al = a_lo_d + ks * 2;
                uint64_t bh = wbase_hi + ks * 2;
                uint64_t bl = wbase_lo + ks * 2;
                uint32_t en0 = (c == 0 && ks == 0) ? 0u : 1u;
                mma_f16_ss(tmem, ah, bh, GEMM_IDESC, en0);
                mma_f16_ss(tmem, al, bh, GEMM_IDESC, 1u);
                mma_f16_ss(tmem, ah, bl, GEMM_IDESC, 1u);
            }
            asm volatile(
                "tcgen05.commit.cta_group::1.mbarrier::arrive::one.shared::cluster.b64 [%0];"
                :: "r"(sbase + SM_MBAR) : "memory");
        }
        __syncthreads();
        {
            uint32_t parity = c & 1;
            asm volatile(
                "{\n\t.reg .pred P1;\n\t"
                "WAIT_LOOP_%=:\n\t"
                "mbarrier.try_wait.parity.acquire.cta.shared::cta.b64 P1, [%0], %1, 0x989680;\n\t"
                "@P1 bra.uni WAIT_DONE_%=;\n\t"
                "bra.uni WAIT_LOOP_%=;\n\t"
                "WAIT_DONE_%=:\n\t}"
                :: "r"(sbase + SM_MBAR), "r"(parity) : "memory");
        }
    }

    asm volatile("tcgen05.fence::after_thread_sync;" ::: "memory");

    // epilogue: warp (wid&3) -> rows, (wid>>2) -> column half
    {
        int r    = (wid & 3) * 32 + lane;
        int grow = row0 + r;
        int cb   = (wid >> 2) * 64;
#pragma unroll
        for (int half = 0; half < 2; half++) {
            int c0 = cb + half * 32;
            uint32_t d[32];
            asm volatile(
                "tcgen05.ld.sync.aligned.32x32b.x32.b32 "
                "{%0,%1,%2,%3,%4,%5,%6,%7,%8,%9,%10,%11,%12,%13,%14,%15,"
                "%16,%17,%18,%19,%20,%21,%22,%23,%24,%25,%26,%27,%28,%29,%30,%31}, [%32];"
                : "=r"(d[0]),"=r"(d[1]),"=r"(d[2]),"=r"(d[3]),"=r"(d[4]),"=r"(d[5]),"=r"(d[6]),"=r"(d[7]),
                  "=r"(d[8]),"=r"(d[9]),"=r"(d[10]),"=r"(d[11]),"=r"(d[12]),"=r"(d[13]),"=r"(d[14]),"=r"(d[15]),
                  "=r"(d[16]),"=r"(d[17]),"=r"(d[18]),"=r"(d[19]),"=r"(d[20]),"=r"(d[21]),"=r"(d[22]),"=r"(d[23]),
                  "=r"(d[24]),"=r"(d[25]),"=r"(d[26]),"=r"(d[27]),"=r"(d[28]),"=r"(d[29]),"=r"(d[30]),"=r"(d[31])
                : "r"(tmem + c0));
            asm volatile("tcgen05.wait::ld.sync.aligned;" ::: "memory");
            if (grow < N_NODES) {
#pragma unroll
                for (int q = 0; q < 32; q += 4) {
                    float4 bv = *reinterpret_cast<const float4*>(&b[c0 + q]);
                    float4 o;
                    o.x = __uint_as_float(d[q + 0]) + bv.x;
                    o.y = __uint_as_float(d[q + 1]) + bv.y;
                    o.z = __uint_as_float(d[q + 2]) + bv.z;
                    o.w = __uint_as_float(d[q + 3]) + bv.w;
                    *reinterpret_cast<float4*>(&g_feat[(size_t)grow * HC + c0 + q]) = o;
                }
            }
        }
    }

    __syncthreads();
    if (wid == 0 && lane == 0) {
        asm volatile("mbarrier.inval.shared.b64 [%0];" :: "r"(sbase + SM_MBAR) : "memory");
    }
    __syncthreads();
    if (wid == 0) {
        asm volatile("tcgen05.relinquish_alloc_permit.cta_group::1.sync.aligned;");
        asm volatile("tcgen05.dealloc.cta_group::1.sync.aligned.b32 %0, %1;"
                     :: "r"(tmem), "r"(128u));
    }
#else
    (void)x; (void)W; (void)b;   // empty on non-sm_103a builds
#endif
}

// ---------------- fallback fp32 SGEMM (measured 190us) -----------------------
__global__ __launch_bounds__(256) void k_gemm_fp32(const float* __restrict__ x,
                                                   const float* __restrict__ W,
                                                   const float* __restrict__ b) {
    if (g_has_tc) return;    // tcgen05 path did the work

    __shared__ float xs[32][132];
    __shared__ float ws[32][132];

    const int tid = threadIdx.x;
    const int tx = tid & 15;
    const int ty = tid >> 4;
    const int row0 = blockIdx.x * 128;

    float acc[8][8];
#pragma unroll
    for (int i = 0; i < 8; i++)
#pragma unroll
        for (int j = 0; j < 8; j++) acc[i][j] = 0.f;

    for (int k0 = 0; k0 < IN_CH; k0 += 32) {
#pragma unroll
        for (int l = 0; l < 4; l++) {
            int idx = tid + l * 256;
            int r  = idx >> 3;
            int kq = idx & 7;
            int grow = row0 + r;
            float4 v = make_float4(0.f, 0.f, 0.f, 0.f);
            if (grow < N_NODES)
                v = *reinterpret_cast<const float4*>(&x[(size_t)grow * IN_CH + k0 + kq * 4]);
            xs[kq * 4 + 0][r] = v.x;
            xs[kq * 4 + 1][r] = v.y;
            xs[kq * 4 + 2][r] = v.z;
            xs[kq * 4 + 3][r] = v.w;
        }
#pragma unroll
        for (int l = 0; l < 4; l++) {
            int idx = tid + l * 256;
            int c  = idx >> 3;
            int kq = idx & 7;
            float4 v = *reinterpret_cast<const float4*>(&W[(size_t)c * IN_CH + k0 + kq * 4]);
            ws[kq * 4 + 0][c] = v.x;
            ws[kq * 4 + 1][c] = v.y;
            ws[kq * 4 + 2][c] = v.z;
            ws[kq * 4 + 3][c] = v.w;
        }
        __syncthreads();

#pragma unroll
        for (int kk = 0; kk < 32; kk++) {
            float a[8], bb[8];
            float4 a0 = *reinterpret_cast<const float4*>(&xs[kk][ty * 8]);
            float4 a1 = *reinterpret_cast<const float4*>(&xs[kk][ty * 8 + 4]);
            float4 b0 = *reinterpret_cast<const float4*>(&ws[kk][tx * 8]);
            float4 b1 = *reinterpret_cast<const float4*>(&ws[kk][tx * 8 + 4]);
            a[0]=a0.x; a[1]=a0.y; a[2]=a0.z; a[3]=a0.w;
            a[4]=a1.x; a[5]=a1.y; a[6]=a1.z; a[7]=a1.w;
            bb[0]=b0.x; bb[1]=b0.y; bb[2]=b0.z; bb[3]=b0.w;
            bb[4]=b1.x; bb[5]=b1.y; bb[6]=b1.z; bb[7]=b1.w;
#pragma unroll
            for (int i = 0; i < 8; i++)
#pragma unroll
                for (int j = 0; j < 8; j++)
                    acc[i][j] = fmaf(a[i], bb[j], acc[i][j]);
        }
        __syncthreads();
    }

#pragma unroll
    for (int i = 0; i < 8; i++) {
        int grow = row0 + ty * 8 + i;
        if (grow >= N_NODES) break;
#pragma unroll
        for (int j = 0; j < 8; j += 4) {
            int col = tx * 8 + j;
            float4 bv = *reinterpret_cast<const float4*>(&b[col]);
            float4 o;
            o.x = acc[i][j + 0] + bv.x;
            o.y = acc[i][j + 1] + bv.y;
            o.z = acc[i][j + 2] + bv.z;
            o.w = acc[i][j + 3] + bv.w;
            *reinterpret_cast<float4*>(&g_feat[(size_t)grow * HC + col]) = o;
        }
    }
}

// ---------------- Kernel 2: per-node attention scalars + init ----------------
__global__ __launch_bounds__(256) void k_epre(const float* __restrict__ att) {
    int warp = (blockIdx.x * blockDim.x + threadIdx.x) >> 5;
    if (warp >= N_NODES) return;
    int lane = threadIdx.x & 31;

    const float4* f4 = reinterpret_cast<const float4*>(g_feat);
    float4 f = f4[(size_t)warp * 32 + lane];
    float4 a0 = *reinterpret_cast<const float4*>(&att[lane * 8]);
    float4 a1 = *reinterpret_cast<const float4*>(&att[lane * 8 + 4]);

    float s0 = f.x * a0.x + f.y * a0.z + f.z * a1.x + f.w * a1.z;
    float s1 = f.x * a0.y + f.y * a0.w + f.z * a1.y + f.w * a1.w;
#pragma unroll
    for (int o = 16; o > 0; o >>= 1) {
        s0 += __shfl_xor_sync(0xffffffffu, s0, o);
        s1 += __shfl_xor_sync(0xffffffffu, s1, o);
    }
    if (lane == 0) {
        g_esrc[warp] = s0;
        g_etar[warp] = s1;
        float z = s0 + s1;
        float lz = z > 0.f ? z : NEG_SLOPE * z;
        g_eself[warp] = expf(lz);
        g_counts[warp] = 0;
    }
}

// ---------------- Kernel 3: histogram of destination nodes -------------------
__global__ __launch_bounds__(256) void k_hist(const void* __restrict__ ei) {
    int i = blockIdx.x * blockDim.x + threadIdx.x;
    if (i >= N_EDGES) return;
    int t, s;
    load_edge(ei, i, t, s);
    if ((unsigned)t >= N_NODES || (unsigned)s >= N_NODES) return;
    atomicAdd(&g_counts[t], 1);
}

// ---------------- Kernels 4a/4b/4c: multi-block exclusive scan ---------------
__global__ __launch_bounds__(1024) void k_scan1() {
    __shared__ int wsum[32];
    int i = blockIdx.x * 1024 + threadIdx.x;
    int lane = threadIdx.x & 31, wd = threadIdx.x >> 5;
    int v = (i < N_NODES) ? g_counts[i] : 0;
    int xv = v;
#pragma unroll
    for (int o = 1; o < 32; o <<= 1) {
        int y = __shfl_up_sync(0xffffffffu, xv, o);
        if (lane >= o) xv += y;
    }
    if (lane == 31) wsum[wd] = xv;
    __syncthreads();
    if (wd == 0) {
        int s = wsum[lane];
#pragma unroll
        for (int o = 1; o < 32; o <<= 1) {
            int y = __shfl_up_sync(0xffffffffu, s, o);
            if (lane >= o) s += y;
        }
        wsum[lane] = s;
    }
    __syncthreads();
    int base = (wd > 0) ? wsum[wd - 1] : 0;
    if (i < N_NODES) g_offsets[i] = base + xv - v;
    if (threadIdx.x == 1023) g_bsums[blockIdx.x] = wsum[31];
}

__global__ __launch_bounds__(128) void k_scan2(int nblocks) {
    __shared__ int sh[128];
    int t = threadIdx.x;
    int v = (t < nblocks) ? g_bsums[t] : 0;
    sh[t] = v;
    __syncthreads();
#pragma unroll
    for (int o = 1; o < 128; o <<= 1) {
        int y = (t >= o) ? sh[t - o] : 0;
        __syncthreads();
        sh[t] += y;
        __syncthreads();
    }
    if (t < nblocks) g_bsums[t] = sh[t] - v;
}

__global__ __launch_bounds__(256) void k_scan3() {
    int i = blockIdx.x * blockDim.x + threadIdx.x;
    if (i >= N_NODES) return;
    int off = g_offsets[i] + g_bsums[i >> 10];
    g_offsets[i] = off;
    g_cursor[i]  = off;
}

// ---------------- Kernel 5: scatter edges into CSR ---------------------------
__global__ __launch_bounds__(256) void k_scatter(const void* __restrict__ ei) {
    int i = blockIdx.x * blockDim.x + threadIdx.x;
    if (i >= N_EDGES) return;
    int t, s;
    load_edge(ei, i, t, s);
    if ((unsigned)t >= N_NODES || (unsigned)s >= N_NODES) return;
    float z = g_esrc[s] + g_etar[t];
    float lz = z > 0.f ? z : NEG_SLOPE * z;
    float e = expf(lz);
    int pos = atomicAdd(&g_cursor[t], 1);
    g_srcs[pos]  = s;
    g_evals[pos] = e;
}

// ---------------- Kernel 6: aggregation, one warp per node -------------------
__global__ __launch_bounds__(256) void k_agg(float* __restrict__ out) {
    int warp = (blockIdx.x * blockDim.x + threadIdx.x) >> 5;
    if (warp >= N_NODES) return;
    int lane = threadIdx.x & 31;

    const float4* f4 = reinterpret_cast<const float4*>(g_feat);
    int off = g_offsets[warp];
    int cnt = g_counts[warp];

    float4 acc = make_float4(0.f, 0.f, 0.f, 0.f);
    float sum_e = 0.f;
    int j = 0;
#pragma unroll 1
    for (; j + 4 <= cnt; j += 4) {
#pragma unroll
        for (int u = 0; u < 4; u++) {
            int s = g_srcs[off + j + u];
            float e = g_evals[off + j + u];
            sum_e += e;
            float4 f = f4[(size_t)s * 32 + lane];
            acc.x = fmaf(e, f.x, acc.x);
            acc.y = fmaf(e, f.y, acc.y);
            acc.z = fmaf(e, f.z, acc.z);
            acc.w = fmaf(e, f.w, acc.w);
        }
    }
    for (; j < cnt; j++) {
        int s = g_srcs[off + j];
        float e = g_evals[off + j];
        sum_e += e;
        float4 f = f4[(size_t)s * 32 + lane];
        acc.x = fmaf(e, f.x, acc.x);
        acc.y = fmaf(e, f.y, acc.y);
        acc.z = fmaf(e, f.z, acc.z);
        acc.w = fmaf(e, f.w, acc.w);
    }

    float es  = g_eself[warp];
    float inv = 1.0f / (sum_e + es);
    float4 fs = f4[(size_t)warp * 32 + lane];
    float4 o;
    o.x = (acc.x + es * fs.x) * inv;
    o.y = (acc.y + es * fs.y) * inv;
    o.z = (acc.z + es * fs.z) * inv;
    o.w = (acc.w + es * fs.w) * inv;
    reinterpret_cast<float4*>(out)[(size_t)warp * 32 + lane] = o;
}

// ---------------- launch ------------------------------------------------------
extern "C" void kernel_launch(void* const* d_in, const int* in_sizes, int n_in,
                              void* d_out, int out_size) {
    const float* x   = nullptr;
    const void*  ei  = nullptr;
    const float* W   = nullptr;
    const float* b   = nullptr;
    const float* att = nullptr;
    for (int i = 0; i < n_in; i++) {
        switch (in_sizes[i]) {
            case 25600000: x   = (const float*)d_in[i]; break;
            case 3200000:  ei  = d_in[i];               break;
            case 32768:    W   = (const float*)d_in[i]; break;
            case 128:      b   = (const float*)d_in[i]; break;
            case 256:      att = (const float*)d_in[i]; break;
            default: break;
        }
    }
    float* out = (float*)d_out;
    (void)out_size;

    k_probe<<<1, 1>>>();
    k_detect<<<1, 32>>>((const long long*)ei);

    int gemm_blocks = (N_NODES + 127) / 128;           // 782
    cudaFuncSetAttribute(k_gemm_tc5, cudaFuncAttributeMaxDynamicSharedMemorySize, SM_TOTAL);
    k_gemm_tc5<<<gemm_blocks, 256, SM_TOTAL>>>(x, W, b);   // no-op unless sm_103a build
    k_gemm_fp32<<<gemm_blocks, 256>>>(x, W, b);            // no-op if tcgen05 ran

    int node_warp_blocks = (N_NODES * 32 + 255) / 256; // 12500
    k_epre<<<node_warp_blocks, 256>>>(att);

    int edge_blocks = (N_EDGES + 255) / 256;           // 6250
    k_hist<<<edge_blocks, 256>>>(ei);

    int scan_blocks = (N_NODES + 1023) / 1024;         // 98
    k_scan1<<<scan_blocks, 1024>>>();
    k_scan2<<<1, 128>>>(scan_blocks);
    k_scan3<<<(N_NODES + 255) / 256, 256>>>();

    k_scatter<<<edge_blocks, 256>>>(ei);

    k_agg<<<node_warp_blocks, 256>>>(out);
}

// round 8
// speedup vs baseline: 2.1092x; 1.0152x over previous
#include <cuda_runtime.h>
#include <cuda_bf16.h>
#include <cstdint>

#define N_NODES 100000
#define N_EDGES 1600000
#define IN_CH   256
#define HC      128        // HEADS*OUT_CH
#define NEG_SLOPE 0.2f

// ---------------- scratch (static device globals; no allocation) -------------
__device__ __align__(16) float g_feat[(size_t)N_NODES * HC];   // 51.2 MB
__device__ float g_esrc[N_NODES];
__device__ float g_etar[N_NODES];
__device__ float g_eself[N_NODES];
__device__ int   g_counts[N_NODES];
__device__ int   g_offsets[N_NODES];
__device__ int   g_cursor[N_NODES];
__device__ int   g_bsums[128];
__device__ int   g_srcs[N_EDGES];
__device__ int   g_is32;

// ---------------- Kernel 0: sniff edge_index dtype ---------------------------
__global__ void k_detect(const long long* __restrict__ p) {
    if (blockIdx.x == 0 && threadIdx.x == 0) {
        int f = 0;
        for (int j = 0; j < 64; j++) {
            long long v = p[j];
            if (v < 0 || v >= (long long)N_NODES) f = 1;
        }
        g_is32 = f;
    }
}

// ---------------- Kernel 0b: zero per-node counts ----------------------------
__global__ __launch_bounds__(1024) void k_zero() {
    int i = blockIdx.x * 1024 + threadIdx.x;
    if (i < N_NODES) g_counts[i] = 0;
}

__device__ __forceinline__ void load_edge(const void* ei, int i, int& t, int& s) {
    if (g_is32) {
        const int* p = (const int*)ei;
        t = p[i];
        s = p[N_EDGES + i];
    } else {
        const long long* p = (const long long*)ei;
        t = (int)p[i];
        s = (int)p[N_EDGES + i];
    }
}

// ======================= tcgen05 GEMM (sm_103a builds only) ==================
#if defined(__CUDA_ARCH_FEAT_SM103_ALL)
__device__ __forceinline__ uint32_t smem_u32(const void* p) {
    uint32_t a;
    asm("{ .reg .u64 t; cvta.to.shared.u64 t, %1; cvt.u32.u64 %0, t; }" : "=r"(a) : "l"(p));
    return a;
}
__device__ __forceinline__ uint32_t elect_one() {
    uint32_t pred;
    asm volatile("{\n\t.reg .pred p;\n\telect.sync _|p, 0xFFFFFFFF;\n\tselp.b32 %0, 1, 0, p;\n\t}"
                 : "=r"(pred));
    return pred;
}
__device__ __forceinline__ uint64_t mk_desc(uint32_t addr) {
    return ((uint64_t)2 << 61) | ((uint64_t)1 << 46) | ((uint64_t)64 << 32) |
           ((uint64_t)1 << 16) | ((uint64_t)(addr >> 4) & 0x3FFF);
}
__device__ __forceinline__ void mma_f16_ss(uint32_t d_tmem, uint64_t a_desc,
                                           uint64_t b_desc, uint32_t idesc, uint32_t en) {
    asm volatile(
        "{\n\t.reg .pred p;\n\tsetp.ne.u32 p, %5, 0;\n\t"
        "tcgen05.mma.cta_group::1.kind::f16 [%0], %1, %2, %3, {%4, %4, %4, %4}, p;\n\t}"
        :: "r"(d_tmem), "l"(a_desc), "l"(b_desc), "r"(idesc), "r"(0u), "r"(en)
        : "memory");
}
__device__ __forceinline__ void mbar_wait(uint32_t mbar, uint32_t parity) {
    asm volatile(
        "{\n\t.reg .pred P1;\n\t"
        "WAIT_LOOP_%=:\n\t"
        "mbarrier.try_wait.parity.acquire.cta.shared::cta.b64 P1, [%0], %1, 0x989680;\n\t"
        "@P1 bra.uni WAIT_DONE_%=;\n\t"
        "bra.uni WAIT_LOOP_%=;\n\t"
        "WAIT_DONE_%=:\n\t}"
        :: "r"(mbar), "r"(parity) : "memory");
}
#endif

#define SWZ(x) ((x) ^ (((x) >> 3) & 0x70))
// idesc kind::f16: dtypeF32(b4) atypeBF16(b7) btypeBF16(b10) N/8<<17 M/16<<24
#define GEMM_IDESC ((1u<<4)|(1u<<7)|(1u<<10)|((HC/8)<<17)|((128/16)<<24))

#define SM_TMEMPTR 0
#define SM_MBAR    8
#define SM_W_HI    1024                    // 128 x 256 bf16 = 64KB
#define SM_W_LO    (SM_W_HI + 65536)
#define SM_A_BASE  (SM_W_LO + 65536)       // 2 buffers x (HI 16K + LO 16K)
#define SM_TOTAL   (SM_A_BASE + 2 * 32768) // 197632 B

// Block tile M=128 x N=128, K=256 in chunks of 64, double-buffered A. bf16x3.
__global__ __launch_bounds__(256, 1)
void k_gemm_tc5(const float* __restrict__ x, const float* __restrict__ W,
                const float* __restrict__ b, const float* __restrict__ att) {
#if defined(__CUDA_ARCH_FEAT_SM103_ALL)
    extern __shared__ char smem[];
    const uint32_t sbase = smem_u32(smem);
    const int tid  = threadIdx.x;
    const int wid  = tid >> 5;
    const int lane = tid & 31;
    const int row0 = blockIdx.x * 128;

    if (wid == 0) {
        asm volatile("tcgen05.alloc.cta_group::1.sync.aligned.shared::cta.b32 [%0], %1;"
                     :: "r"(sbase + SM_TMEMPTR), "r"(128u) : "memory");
    }
    if (wid == 0 && lane == 0) {
        asm volatile("mbarrier.init.shared.b64 [%0], %1;"
                     :: "r"(sbase + SM_MBAR), "r"(1u) : "memory");
    }
    __syncthreads();
    uint32_t tmem;
    asm volatile("ld.shared.b32 %0, [%1];" : "=r"(tmem) : "r"(sbase + SM_TMEMPTR));

    // W (128n x 256k) -> SW128 blocked atoms, hi/lo bf16 planes (once per CTA).
    for (int g = tid; g < 4096; g += 256) {
        int row = g >> 5;
        int k   = (g & 31) * 8;
        float4 v0 = *reinterpret_cast<const float4*>(&W[(size_t)row * IN_CH + k]);
        float4 v1 = *reinterpret_cast<const float4*>(&W[(size_t)row * IN_CH + k + 4]);
        float f[8] = {v0.x, v0.y, v0.z, v0.w, v1.x, v1.y, v1.z, v1.w};
        __nv_bfloat16 hb[8], lb[8];
#pragma unroll
        for (int i = 0; i < 8; i++) {
            hb[i] = __float2bfloat16_rn(f[i]);
            lb[i] = __float2bfloat16_rn(f[i] - __bfloat162float(hb[i]));
        }
        uint32_t atom = (row >> 3) + (k >> 6) * 16;
        uint32_t byte = atom * 1024 + (row & 7) * 128 + (k & 63) * 2;
        uint32_t sw = SWZ(byte);
        *reinterpret_cast<uint4*>(smem + SM_W_HI + sw) = *reinterpret_cast<uint4*>(hb);
        *reinterpret_cast<uint4*>(smem + SM_W_LO + sw) = *reinterpret_cast<uint4*>(lb);
    }

    const uint64_t w_hi_d = mk_desc(sbase + SM_W_HI);
    const uint64_t w_lo_d = mk_desc(sbase + SM_W_LO);

    int nwaits = 0;   // parity of next wait = nwaits & 1

#pragma unroll 1
    for (int c = 0; c < 4; c++) {
        int buf = c & 1;
        uint32_t a_hi_off = SM_A_BASE + buf * 32768;
        uint32_t a_lo_off = a_hi_off + 16384;

        if (c >= 2) {              // free this buffer: chunk c-2's MMAs must be done
            mbar_wait(sbase + SM_MBAR, nwaits & 1);
            nwaits++;
        }

        // A chunk: 128 rows x 64 k -> hi/lo planes (16 atoms)
        for (int g = tid; g < 1024; g += 256) {
            int row = g >> 3;
            int k   = (g & 7) * 8;
            int grow = row0 + row;
            float f[8] = {0.f, 0.f, 0.f, 0.f, 0.f, 0.f, 0.f, 0.f};
            if (grow < N_NODES) {
                float4 v0 = *reinterpret_cast<const float4*>(&x[(size_t)grow * IN_CH + c * 64 + k]);
                float4 v1 = *reinterpret_cast<const float4*>(&x[(size_t)grow * IN_CH + c * 64 + k + 4]);
                f[0]=v0.x; f[1]=v0.y; f[2]=v0.z; f[3]=v0.w;
                f[4]=v1.x; f[5]=v1.y; f[6]=v1.z; f[7]=v1.w;
            }
            __nv_bfloat16 hb[8], lb[8];
#pragma unroll
            for (int i = 0; i < 8; i++) {
                hb[i] = __float2bfloat16_rn(f[i]);
                lb[i] = __float2bfloat16_rn(f[i] - __bfloat162float(hb[i]));
            }
            uint32_t byte = (row >> 3) * 1024 + (row & 7) * 128 + k * 2;
            uint32_t sw = SWZ(byte);
            *reinterpret_cast<uint4*>(smem + a_hi_off + sw) = *reinterpret_cast<uint4*>(hb);
            *reinterpret_cast<uint4*>(smem + a_lo_off + sw) = *reinterpret_cast<uint4*>(lb);
        }
        asm volatile("fence.proxy.async.shared::cta;" ::: "memory");
        __syncthreads();

        if (wid == 0 && elect_one()) {
            uint64_t a_hi_d = mk_desc(sbase + a_hi_off);
            uint64_t a_lo_d = mk_desc(sbase + a_lo_off);
            uint64_t wbase_hi = w_hi_d + (uint64_t)c * 1024;   // 16 atoms/chunk
            uint64_t wbase_lo = w_lo_d + (uint64_t)c * 1024;
#pragma unroll
            for (int ks = 0; ks < 4; ks++) {                    // K=16 per mma
                uint64_t ah = a_hi_d + ks * 2;
                uint64_t al = a_lo_d + ks * 2;
                uint64_t bh = wbase_hi + ks * 2;
                uint64_t bl = wbase_lo + ks * 2;
                uint32_t en0 = (c == 0 && ks == 0) ? 0u : 1u;
                mma_f16_ss(tmem, ah, bh, GEMM_IDESC, en0);
                mma_f16_ss(tmem, al, bh, GEMM_IDESC, 1u);
                mma_f16_ss(tmem, ah, bl, GEMM_IDESC, 1u);
            }
            asm volatile(
                "tcgen05.commit.cta_group::1.mbarrier::arrive::one.shared::cluster.b64 [%0];"
                :: "r"(sbase + SM_MBAR) : "memory");
        }
        __syncthreads();
    }

    // drain remaining commits (chunks 2 and 3)
    mbar_wait(sbase + SM_MBAR, nwaits & 1); nwaits++;
    mbar_wait(sbase + SM_MBAR, nwaits & 1); nwaits++;
    asm volatile("tcgen05.fence::after_thread_sync;" ::: "memory");

    // epilogue: warp pair (w, w+4) covers rows (wid&3)*32+lane; cols split 64/64.
    // Each lane holds its full 64-col segment -> partial att-dots per lane.
    int r    = (wid & 3) * 32 + lane;
    int grow = row0 + r;
    int cb   = (wid >> 2) * 64;
    float s0 = 0.f, s1 = 0.f;
#pragma unroll
    for (int half = 0; half < 2; half++) {
        int c0 = cb + half * 32;
        uint32_t d[32];
        asm volatile(
            "tcgen05.ld.sync.aligned.32x32b.x32.b32 "
            "{%0,%1,%2,%3,%4,%5,%6,%7,%8,%9,%10,%11,%12,%13,%14,%15,"
            "%16,%17,%18,%19,%20,%21,%22,%23,%24,%25,%26,%27,%28,%29,%30,%31}, [%32];"
            : "=r"(d[0]),"=r"(d[1]),"=r"(d[2]),"=r"(d[3]),"=r"(d[4]),"=r"(d[5]),"=r"(d[6]),"=r"(d[7]),
              "=r"(d[8]),"=r"(d[9]),"=r"(d[10]),"=r"(d[11]),"=r"(d[12]),"=r"(d[13]),"=r"(d[14]),"=r"(d[15]),
              "=r"(d[16]),"=r"(d[17]),"=r"(d[18]),"=r"(d[19]),"=r"(d[20]),"=r"(d[21]),"=r"(d[22]),"=r"(d[23]),
              "=r"(d[24]),"=r"(d[25]),"=r"(d[26]),"=r"(d[27]),"=r"(d[28]),"=r"(d[29]),"=r"(d[30]),"=r"(d[31])
            : "r"(tmem + c0));
        asm volatile("tcgen05.wait::ld.sync.aligned;" ::: "memory");
        if (grow < N_NODES) {
#pragma unroll
            for (int q = 0; q < 32; q += 4) {
                float4 bv = *reinterpret_cast<const float4*>(&b[c0 + q]);
                float4 o;
                o.x = __uint_as_float(d[q + 0]) + bv.x;
                o.y = __uint_as_float(d[q + 1]) + bv.y;
                o.z = __uint_as_float(d[q + 2]) + bv.z;
                o.w = __uint_as_float(d[q + 3]) + bv.w;
                *reinterpret_cast<float4*>(&g_feat[(size_t)grow * HC + c0 + q]) = o;
                const float* ov = reinterpret_cast<const float*>(&o);
#pragma unroll
                for (int i = 0; i < 4; i++) {
                    int col = c0 + q + i;
                    s0 = fmaf(ov[i], att[2 * col],     s0);
                    s1 = fmaf(ov[i], att[2 * col + 1], s1);
                }
            }
        }
    }

    // cross-warp-pair reduction through smem (A buffers are free now)
    float* sh = reinterpret_cast<float*>(smem + SM_A_BASE);
    __syncthreads();
    if (wid < 4) { sh[r * 2] = s0; sh[r * 2 + 1] = s1; }
    __syncthreads();
    if (wid >= 4 && grow < N_NODES) {
        float t0 = s0 + sh[r * 2];
        float t1 = s1 + sh[r * 2 + 1];
        g_esrc[grow] = t0;
        g_etar[grow] = t1;
        float z = t0 + t1;
        float lz = z > 0.f ? z : NEG_SLOPE * z;
        g_eself[grow] = expf(lz);
    }

    __syncthreads();
    if (wid == 0 && lane == 0) {
        asm volatile("mbarrier.inval.shared.b64 [%0];" :: "r"(sbase + SM_MBAR) : "memory");
    }
    __syncthreads();
    if (wid == 0) {
        asm volatile("tcgen05.relinquish_alloc_permit.cta_group::1.sync.aligned;");
        asm volatile("tcgen05.dealloc.cta_group::1.sync.aligned.b32 %0, %1;"
                     :: "r"(tmem), "r"(128u));
    }
#else
    (void)x; (void)W; (void)b; (void)att;
#endif
}

// -------- fallback fp32 SGEMM + epre (compiled only for non-sm_103a SASS) ----
__global__ __launch_bounds__(256) void k_gemm_fp32(const float* __restrict__ x,
                                                   const float* __restrict__ W,
                                                   const float* __restrict__ b) {
#if !defined(__CUDA_ARCH_FEAT_SM103_ALL)
    __shared__ float xs[32][132];
    __shared__ float ws[32][132];

    const int tid = threadIdx.x;
    const int tx = tid & 15;
    const int ty = tid >> 4;
    const int row0 = blockIdx.x * 128;

    float acc[8][8];
#pragma unroll
    for (int i = 0; i < 8; i++)
#pragma unroll
        for (int j = 0; j < 8; j++) acc[i][j] = 0.f;

    for (int k0 = 0; k0 < IN_CH; k0 += 32) {
#pragma unroll
        for (int l = 0; l < 4; l++) {
            int idx = tid + l * 256;
            int r  = idx >> 3;
            int kq = idx & 7;
            int grow = row0 + r;
            float4 v = make_float4(0.f, 0.f, 0.f, 0.f);
            if (grow < N_NODES)
                v = *reinterpret_cast<const float4*>(&x[(size_t)grow * IN_CH + k0 + kq * 4]);
            xs[kq * 4 + 0][r] = v.x;
            xs[kq * 4 + 1][r] = v.y;
            xs[kq * 4 + 2][r] = v.z;
            xs[kq * 4 + 3][r] = v.w;
        }
#pragma unroll
        for (int l = 0; l < 4; l++) {
            int idx = tid + l * 256;
            int cc = idx >> 3;
            int kq = idx & 7;
            float4 v = *reinterpret_cast<const float4*>(&W[(size_t)cc * IN_CH + k0 + kq * 4]);
            ws[kq * 4 + 0][cc] = v.x;
            ws[kq * 4 + 1][cc] = v.y;
            ws[kq * 4 + 2][cc] = v.z;
            ws[kq * 4 + 3][cc] = v.w;
        }
        __syncthreads();

#pragma unroll
        for (int kk = 0; kk < 32; kk++) {
            float a[8], bb[8];
            float4 a0 = *reinterpret_cast<const float4*>(&xs[kk][ty * 8]);
            float4 a1 = *reinterpret_cast<const float4*>(&xs[kk][ty * 8 + 4]);
            float4 b0 = *reinterpret_cast<const float4*>(&ws[kk][tx * 8]);
            float4 b1 = *reinterpret_cast<const float4*>(&ws[kk][tx * 8 + 4]);
            a[0]=a0.x; a[1]=a0.y; a[2]=a0.z; a[3]=a0.w;
            a[4]=a1.x; a[5]=a1.y; a[6]=a1.z; a[7]=a1.w;
            bb[0]=b0.x; bb[1]=b0.y; bb[2]=b0.z; bb[3]=b0.w;
            bb[4]=b1.x; bb[5]=b1.y; bb[6]=b1.z; bb[7]=b1.w;
#pragma unroll
            for (int i = 0; i < 8; i++)
#pragma unroll
                for (int j = 0; j < 8; j++)
                    acc[i][j] = fmaf(a[i], bb[j], acc[i][j]);
        }
        __syncthreads();
    }

#pragma unroll
    for (int i = 0; i < 8; i++) {
        int grow = row0 + ty * 8 + i;
        if (grow >= N_NODES) break;
#pragma unroll
        for (int j = 0; j < 8; j += 4) {
            int col = tx * 8 + j;
            float4 bv = *reinterpret_cast<const float4*>(&b[col]);
            float4 o;
            o.x = acc[i][j + 0] + bv.x;
            o.y = acc[i][j + 1] + bv.y;
            o.z = acc[i][j + 2] + bv.z;
            o.w = acc[i][j + 3] + bv.w;
            *reinterpret_cast<float4*>(&g_feat[(size_t)grow * HC + col]) = o;
        }
    }
#else
    (void)x; (void)W; (void)b;
#endif
}

__global__ __launch_bounds__(256) void k_epre(const float* __restrict__ att) {
#if !defined(__CUDA_ARCH_FEAT_SM103_ALL)
    int warp = (blockIdx.x * blockDim.x + threadIdx.x) >> 5;
    if (warp >= N_NODES) return;
    int lane = threadIdx.x & 31;

    const float4* f4 = reinterpret_cast<const float4*>(g_feat);
    float4 f = f4[(size_t)warp * 32 + lane];
    float4 a0 = *reinterpret_cast<const float4*>(&att[lane * 8]);
    float4 a1 = *reinterpret_cast<const float4*>(&att[lane * 8 + 4]);

    float s0 = f.x * a0.x + f.y * a0.z + f.z * a1.x + f.w * a1.z;
    float s1 = f.x * a0.y + f.y * a0.w + f.z * a1.y + f.w * a1.w;
#pragma unroll
    for (int o = 16; o > 0; o >>= 1) {
        s0 += __shfl_xor_sync(0xffffffffu, s0, o);
        s1 += __shfl_xor_sync(0xffffffffu, s1, o);
    }
    if (lane == 0) {
        g_esrc[warp] = s0;
        g_etar[warp] = s1;
        float z = s0 + s1;
        float lz = z > 0.f ? z : NEG_SLOPE * z;
        g_eself[warp] = expf(lz);
    }
#else
    (void)att;
#endif
}

// ---------------- Kernel 3: histogram of destination nodes -------------------
__global__ __launch_bounds__(256) void k_hist(const void* __restrict__ ei) {
    int i = blockIdx.x * blockDim.x + threadIdx.x;
    if (i >= N_EDGES) return;
    int t, s;
    load_edge(ei, i, t, s);
    if ((unsigned)t >= N_NODES || (unsigned)s >= N_NODES) return;
    atomicAdd(&g_counts[t], 1);
}

// ---------------- Kernels 4a/4b/4c: multi-block exclusive scan ---------------
__global__ __launch_bounds__(1024) void k_scan1() {
    __shared__ int wsum[32];
    int i = blockIdx.x * 1024 + threadIdx.x;
    int lane = threadIdx.x & 31, wd = threadIdx.x >> 5;
    int v = (i < N_NODES) ? g_counts[i] : 0;
    int xv = v;
#pragma unroll
    for (int o = 1; o < 32; o <<= 1) {
        int y = __shfl_up_sync(0xffffffffu, xv, o);
        if (lane >= o) xv += y;
    }
    if (lane == 31) wsum[wd] = xv;
    __syncthreads();
    if (wd == 0) {
        int s = wsum[lane];
#pragma unroll
        for (int o = 1; o < 32; o <<= 1) {
            int y = __shfl_up_sync(0xffffffffu, s, o);
            if (lane >= o) s += y;
        }
        wsum[lane] = s;
    }
    __syncthreads();
    int base = (wd > 0) ? wsum[wd - 1] : 0;
    if (i < N_NODES) g_offsets[i] = base + xv - v;
    if (threadIdx.x == 1023) g_bsums[blockIdx.x] = wsum[31];
}

__global__ __launch_bounds__(128) void k_scan2(int nblocks) {
    __shared__ int sh[128];
    int t = threadIdx.x;
    int v = (t < nblocks) ? g_bsums[t] : 0;
    sh[t] = v;
    __syncthreads();
#pragma unroll
    for (int o = 1; o < 128; o <<= 1) {
        int y = (t >= o) ? sh[t - o] : 0;
        __syncthreads();
        sh[t] += y;
        __syncthreads();
    }
    if (t < nblocks) g_bsums[t] = sh[t] - v;
}

__global__ __launch_bounds__(256) void k_scan3() {
    int i = blockIdx.x * blockDim.x + threadIdx.x;
    if (i >= N_NODES) return;
    int off = g_offsets[i] + g_bsums[i >> 10];
    g_offsets[i] = off;
    g_cursor[i]  = off;
}

// ---------------- Kernel 5: scatter edge sources into CSR --------------------
__global__ __launch_bounds__(256) void k_scatter(const void* __restrict__ ei) {
    int i = blockIdx.x * blockDim.x + threadIdx.x;
    if (i >= N_EDGES) return;
    int t, s;
    load_edge(ei, i, t, s);
    if ((unsigned)t >= N_NODES || (unsigned)s >= N_NODES) return;
    int pos = atomicAdd(&g_cursor[t], 1);
    g_srcs[pos] = s;
}

// ---------------- Kernel 6: aggregation, one warp per node -------------------
__global__ __launch_bounds__(256) void k_agg(float* __restrict__ out) {
    int warp = (blockIdx.x * blockDim.x + threadIdx.x) >> 5;
    if (warp >= N_NODES) return;
    int lane = threadIdx.x & 31;

    const float4* f4 = reinterpret_cast<const float4*>(g_feat);
    int off = g_offsets[warp];
    int cnt = g_counts[warp];
    float etar = g_etar[warp];

    float4 acc = make_float4(0.f, 0.f, 0.f, 0.f);
    float sum_e = 0.f;
    int j = 0;
#pragma unroll 1
    for (; j + 4 <= cnt; j += 4) {
#pragma unroll
        for (int u = 0; u < 4; u++) {
            int s = g_srcs[off + j + u];
            float z = g_esrc[s] + etar;
            float lz = z > 0.f ? z : NEG_SLOPE * z;
            float e = expf(lz);
            sum_e += e;
            float4 f = f4[(size_t)s * 32 + lane];
            acc.x = fmaf(e, f.x, acc.x);
            acc.y = fmaf(e, f.y, acc.y);
            acc.z = fmaf(e, f.z, acc.z);
            acc.w = fmaf(e, f.w, acc.w);
        }
    }
    for (; j < cnt; j++) {
        int s = g_srcs[off + j];
        float z = g_esrc[s] + etar;
        float lz = z > 0.f ? z : NEG_SLOPE * z;
        float e = expf(lz);
        sum_e += e;
        float4 f = f4[(size_t)s * 32 + lane];
        acc.x = fmaf(e, f.x, acc.x);
        acc.y = fmaf(e, f.y, acc.y);
        acc.z = fmaf(e, f.z, acc.z);
        acc.w = fmaf(e, f.w, acc.w);
    }

    float es  = g_eself[warp];
    float inv = 1.0f / (sum_e + es);
    float4 fs = f4[(size_t)warp * 32 + lane];
    float4 o;
    o.x = (acc.x + es * fs.x) * inv;
    o.y = (acc.y + es * fs.y) * inv;
    o.z = (acc.z + es * fs.z) * inv;
    o.w = (acc.w + es * fs.w) * inv;
    reinterpret_cast<float4*>(out)[(size_t)warp * 32 + lane] = o;
}

// ---------------- launch ------------------------------------------------------
extern "C" void kernel_launch(void* const* d_in, const int* in_sizes, int n_in,
                              void* d_out, int out_size) {
    const float* x   = nullptr;
    const void*  ei  = nullptr;
    const float* W   = nullptr;
    const float* b   = nullptr;
    const float* att = nullptr;
    for (int i = 0; i < n_in; i++) {
        switch (in_sizes[i]) {
            case 25600000: x   = (const float*)d_in[i]; break;
            case 3200000:  ei  = d_in[i];               break;
            case 32768:    W   = (const float*)d_in[i]; break;
            case 128:      b   = (const float*)d_in[i]; break;
            case 256:      att = (const float*)d_in[i]; break;
            default: break;
        }
    }
    float* out = (float*)d_out;
    (void)out_size;

    k_detect<<<1, 32>>>((const long long*)ei);
    k_zero<<<(N_NODES + 1023) / 1024, 1024>>>();

    int gemm_blocks = (N_NODES + 127) / 128;           // 782
    cudaFuncSetAttribute(k_gemm_tc5, cudaFuncAttributeMaxDynamicSharedMemorySize, SM_TOTAL);
    k_gemm_tc5<<<gemm_blocks, 256, SM_TOTAL>>>(x, W, b, att);  // empty on non-103a SASS
    k_gemm_fp32<<<gemm_blocks, 256>>>(x, W, b);                // empty on 103a SASS
    k_epre<<<(N_NODES * 32 + 255) / 256, 256>>>(att);          // empty on 103a SASS

    int edge_blocks = (N_EDGES + 255) / 256;           // 6250
    k_hist<<<edge_blocks, 256>>>(ei);

    int scan_blocks = (N_NODES + 1023) / 1024;         // 98
    k_scan1<<<scan_blocks, 1024>>>();
    k_scan2<<<1, 128>>>(scan_blocks);
    k_scan3<<<(N_NODES + 255) / 256, 256>>>();

    k_scatter<<<edge_blocks, 256>>>(ei);

    int node_warp_blocks = (N_NODES * 32 + 255) / 256; // 12500
    k_agg<<<node_warp_blocks, 256>>>(out);
}

// round 9
// speedup vs baseline: 2.3813x; 1.1290x over previous
#include <cuda_runtime.h>
#include <cuda_bf16.h>
#include <cstdint>

#define N_NODES 100000
#define N_EDGES 1600000
#define IN_CH   256
#define HC      128        // HEADS*OUT_CH
#define NEG_SLOPE 0.2f

// ---------------- scratch (static device globals; no allocation) -------------
__device__ __align__(16) float g_feat[(size_t)N_NODES * HC];   // 51.2 MB
__device__ float g_esrc[N_NODES];
__device__ float g_etar[N_NODES];
__device__ float g_eself[N_NODES];
__device__ int   g_counts[N_NODES];
__device__ int   g_offsets[N_NODES];
__device__ int   g_cursor[N_NODES];
__device__ int   g_bsums[128];
__device__ int   g_srcs[N_EDGES];
__device__ int   g_is32;

// ---------------- Kernel 0: sniff edge_index dtype ---------------------------
__global__ void k_detect(const long long* __restrict__ p) {
    if (blockIdx.x == 0 && threadIdx.x == 0) {
        int f = 0;
        for (int j = 0; j < 64; j++) {
            long long v = p[j];
            if (v < 0 || v >= (long long)N_NODES) f = 1;
        }
        g_is32 = f;
    }
}

// ---------------- Kernel 0b: zero per-node counts ----------------------------
__global__ __launch_bounds__(1024) void k_zero() {
    int i = blockIdx.x * 1024 + threadIdx.x;
    if (i < N_NODES) g_counts[i] = 0;
}

__device__ __forceinline__ void load_edge(const void* ei, int i, int& t, int& s) {
    if (g_is32) {
        const int* p = (const int*)ei;
        t = p[i];
        s = p[N_EDGES + i];
    } else {
        const long long* p = (const long long*)ei;
        t = (int)p[i];
        s = (int)p[N_EDGES + i];
    }
}

// ======================= tcgen05 GEMM (sm_103a builds only) ==================
#if defined(__CUDA_ARCH_FEAT_SM103_ALL)
__device__ __forceinline__ uint32_t smem_u32(const void* p) {
    uint32_t a;
    asm("{ .reg .u64 t; cvta.to.shared.u64 t, %1; cvt.u32.u64 %0, t; }" : "=r"(a) : "l"(p));
    return a;
}
__device__ __forceinline__ uint32_t elect_one() {
    uint32_t pred;
    asm volatile("{\n\t.reg .pred p;\n\telect.sync _|p, 0xFFFFFFFF;\n\tselp.b32 %0, 1, 0, p;\n\t}"
                 : "=r"(pred));
    return pred;
}
__device__ __forceinline__ uint64_t mk_desc(uint32_t addr) {
    return ((uint64_t)2 << 61) | ((uint64_t)1 << 46) | ((uint64_t)64 << 32) |
           ((uint64_t)1 << 16) | ((uint64_t)(addr >> 4) & 0x3FFF);
}
__device__ __forceinline__ void mma_f16_ss(uint32_t d_tmem, uint64_t a_desc,
                                           uint64_t b_desc, uint32_t idesc, uint32_t en) {
    asm volatile(
        "{\n\t.reg .pred p;\n\tsetp.ne.u32 p, %5, 0;\n\t"
        "tcgen05.mma.cta_group::1.kind::f16 [%0], %1, %2, %3, {%4, %4, %4, %4}, p;\n\t}"
        :: "r"(d_tmem), "l"(a_desc), "l"(b_desc), "r"(idesc), "r"(0u), "r"(en)
        : "memory");
}
__device__ __forceinline__ void mbar_wait(uint32_t mbar, uint32_t parity) {
    asm volatile(
        "{\n\t.reg .pred P1;\n\t"
        "WAIT_LOOP_%=:\n\t"
        "mbarrier.try_wait.parity.acquire.cta.shared::cta.b64 P1, [%0], %1, 0x989680;\n\t"
        "@P1 bra.uni WAIT_DONE_%=;\n\t"
        "bra.uni WAIT_LOOP_%=;\n\t"
        "WAIT_DONE_%=:\n\t}"
        :: "r"(mbar), "r"(parity) : "memory");
}
#endif

#define SWZ(x) ((x) ^ (((x) >> 3) & 0x70))
// idesc kind::f16: dtypeF32(b4) atypeBF16(b7) btypeBF16(b10) N/8<<17 M/16<<24
#define GEMM_IDESC ((1u<<4)|(1u<<7)|(1u<<10)|((HC/8)<<17)|((128/16)<<24))

#define SM_TMEMPTR 0
#define SM_MBAR    8
#define SM_W_HI    1024                    // 128 x 256 bf16 = 64KB
#define SM_W_LO    (SM_W_HI + 65536)
#define SM_A_BASE  (SM_W_LO + 65536)       // 2 buffers x (HI 16K + LO 16K)
#define SM_TOTAL   (SM_A_BASE + 2 * 32768) // 197632 B

// Block tile M=128 x N=128, K=256 in chunks of 64, double-buffered A. bf16x3.
// 512 threads: 16 warps for loads/convert/epilogue.
__global__ __launch_bounds__(512, 1)
void k_gemm_tc5(const float* __restrict__ x, const float* __restrict__ W,
                const float* __restrict__ b, const float* __restrict__ att) {
#if defined(__CUDA_ARCH_FEAT_SM103_ALL)
    extern __shared__ char smem[];
    const uint32_t sbase = smem_u32(smem);
    const int tid  = threadIdx.x;
    const int wid  = tid >> 5;
    const int lane = tid & 31;
    const int row0 = blockIdx.x * 128;

    if (wid == 0) {
        asm volatile("tcgen05.alloc.cta_group::1.sync.aligned.shared::cta.b32 [%0], %1;"
                     :: "r"(sbase + SM_TMEMPTR), "r"(128u) : "memory");
    }
    if (wid == 0 && lane == 0) {
        asm volatile("mbarrier.init.shared.b64 [%0], %1;"
                     :: "r"(sbase + SM_MBAR), "r"(1u) : "memory");
    }
    __syncthreads();
    uint32_t tmem;
    asm volatile("ld.shared.b32 %0, [%1];" : "=r"(tmem) : "r"(sbase + SM_TMEMPTR));

    // W (128n x 256k) -> SW128 blocked atoms, hi/lo bf16 planes (once per CTA).
    for (int g = tid; g < 4096; g += 512) {
        int row = g >> 5;
        int k   = (g & 31) * 8;
        float4 v0 = *reinterpret_cast<const float4*>(&W[(size_t)row * IN_CH + k]);
        float4 v1 = *reinterpret_cast<const float4*>(&W[(size_t)row * IN_CH + k + 4]);
        float f[8] = {v0.x, v0.y, v0.z, v0.w, v1.x, v1.y, v1.z, v1.w};
        __nv_bfloat16 hb[8], lb[8];
#pragma unroll
        for (int i = 0; i < 8; i++) {
            hb[i] = __float2bfloat16_rn(f[i]);
            lb[i] = __float2bfloat16_rn(f[i] - __bfloat162float(hb[i]));
        }
        uint32_t atom = (row >> 3) + (k >> 6) * 16;
        uint32_t byte = atom * 1024 + (row & 7) * 128 + (k & 63) * 2;
        uint32_t sw = SWZ(byte);
        *reinterpret_cast<uint4*>(smem + SM_W_HI + sw) = *reinterpret_cast<uint4*>(hb);
        *reinterpret_cast<uint4*>(smem + SM_W_LO + sw) = *reinterpret_cast<uint4*>(lb);
    }

    const uint64_t w_hi_d = mk_desc(sbase + SM_W_HI);
    const uint64_t w_lo_d = mk_desc(sbase + SM_W_LO);

    int nwaits = 0;

#pragma unroll 1
    for (int c = 0; c < 4; c++) {
        int buf = c & 1;
        uint32_t a_hi_off = SM_A_BASE + buf * 32768;
        uint32_t a_lo_off = a_hi_off + 16384;

        if (c >= 2) {              // free this buffer: chunk c-2's MMAs must be done
            mbar_wait(sbase + SM_MBAR, nwaits & 1);
            nwaits++;
        }

        // A chunk: 128 rows x 64 k -> hi/lo planes (16 atoms); 2 iters/thread
        for (int g = tid; g < 1024; g += 512) {
            int row = g >> 3;
            int k   = (g & 7) * 8;
            int grow = row0 + row;
            float f[8] = {0.f, 0.f, 0.f, 0.f, 0.f, 0.f, 0.f, 0.f};
            if (grow < N_NODES) {
                float4 v0 = *reinterpret_cast<const float4*>(&x[(size_t)grow * IN_CH + c * 64 + k]);
                float4 v1 = *reinterpret_cast<const float4*>(&x[(size_t)grow * IN_CH + c * 64 + k + 4]);
                f[0]=v0.x; f[1]=v0.y; f[2]=v0.z; f[3]=v0.w;
                f[4]=v1.x; f[5]=v1.y; f[6]=v1.z; f[7]=v1.w;
            }
            __nv_bfloat16 hb[8], lb[8];
#pragma unroll
            for (int i = 0; i < 8; i++) {
                hb[i] = __float2bfloat16_rn(f[i]);
                lb[i] = __float2bfloat16_rn(f[i] - __bfloat162float(hb[i]));
            }
            uint32_t byte = (row >> 3) * 1024 + (row & 7) * 128 + k * 2;
            uint32_t sw = SWZ(byte);
            *reinterpret_cast<uint4*>(smem + a_hi_off + sw) = *reinterpret_cast<uint4*>(hb);
            *reinterpret_cast<uint4*>(smem + a_lo_off + sw) = *reinterpret_cast<uint4*>(lb);
        }
        asm volatile("fence.proxy.async.shared::cta;" ::: "memory");
        __syncthreads();

        if (wid == 0 && elect_one()) {
            uint64_t a_hi_d = mk_desc(sbase + a_hi_off);
            uint64_t a_lo_d = mk_desc(sbase + a_lo_off);
            uint64_t wbase_hi = w_hi_d + (uint64_t)c * 1024;   // 16 atoms/chunk
            uint64_t wbase_lo = w_lo_d + (uint64_t)c * 1024;
#pragma unroll
            for (int ks = 0; ks < 4; ks++) {                    // K=16 per mma
                uint64_t ah = a_hi_d + ks * 2;
                uint64_t al = a_lo_d + ks * 2;
                uint64_t bh = wbase_hi + ks * 2;
                uint64_t bl = wbase_lo + ks * 2;
                uint32_t en0 = (c == 0 && ks == 0) ? 0u : 1u;
                mma_f16_ss(tmem, ah, bh, GEMM_IDESC, en0);
                mma_f16_ss(tmem, al, bh, GEMM_IDESC, 1u);
                mma_f16_ss(tmem, ah, bl, GEMM_IDESC, 1u);
            }
            asm volatile(
                "tcgen05.commit.cta_group::1.mbarrier::arrive::one.shared::cluster.b64 [%0];"
                :: "r"(sbase + SM_MBAR) : "memory");
        }
        __syncthreads();
    }

    // drain remaining commits (chunks 2 and 3)
    mbar_wait(sbase + SM_MBAR, nwaits & 1); nwaits++;
    mbar_wait(sbase + SM_MBAR, nwaits & 1); nwaits++;
    asm volatile("tcgen05.fence::after_thread_sync;" ::: "memory");

    // epilogue: 16 warps. Subpartition (row group) = wid&3 (HW-forced for LDTM),
    // column quarter = wid>>2. One LDTM x32 per warp (32 cols x 32 rows).
    int rg   = wid & 3;
    int q    = wid >> 2;          // 0..3
    int r    = rg * 32 + lane;
    int grow = row0 + r;
    int c0   = q * 32;
    float s0 = 0.f, s1 = 0.f;
    {
        uint32_t d[32];
        asm volatile(
            "tcgen05.ld.sync.aligned.32x32b.x32.b32 "
            "{%0,%1,%2,%3,%4,%5,%6,%7,%8,%9,%10,%11,%12,%13,%14,%15,"
            "%16,%17,%18,%19,%20,%21,%22,%23,%24,%25,%26,%27,%28,%29,%30,%31}, [%32];"
            : "=r"(d[0]),"=r"(d[1]),"=r"(d[2]),"=r"(d[3]),"=r"(d[4]),"=r"(d[5]),"=r"(d[6]),"=r"(d[7]),
              "=r"(d[8]),"=r"(d[9]),"=r"(d[10]),"=r"(d[11]),"=r"(d[12]),"=r"(d[13]),"=r"(d[14]),"=r"(d[15]),
              "=r"(d[16]),"=r"(d[17]),"=r"(d[18]),"=r"(d[19]),"=r"(d[20]),"=r"(d[21]),"=r"(d[22]),"=r"(d[23]),
              "=r"(d[24]),"=r"(d[25]),"=r"(d[26]),"=r"(d[27]),"=r"(d[28]),"=r"(d[29]),"=r"(d[30]),"=r"(d[31])
            : "r"(tmem + c0));
        asm volatile("tcgen05.wait::ld.sync.aligned;" ::: "memory");
        if (grow < N_NODES) {
#pragma unroll
            for (int qq = 0; qq < 32; qq += 4) {
                float4 bv = *reinterpret_cast<const float4*>(&b[c0 + qq]);
                float4 o;
                o.x = __uint_as_float(d[qq + 0]) + bv.x;
                o.y = __uint_as_float(d[qq + 1]) + bv.y;
                o.z = __uint_as_float(d[qq + 2]) + bv.z;
                o.w = __uint_as_float(d[qq + 3]) + bv.w;
                *reinterpret_cast<float4*>(&g_feat[(size_t)grow * HC + c0 + qq]) = o;
                const float* ov = reinterpret_cast<const float*>(&o);
#pragma unroll
                for (int i = 0; i < 4; i++) {
                    int col = c0 + qq + i;
                    s0 = fmaf(ov[i], att[2 * col],     s0);
                    s1 = fmaf(ov[i], att[2 * col + 1], s1);
                }
            }
        }
    }

    // reduce att-dot partials across the 4 quarter-warps per row (A bufs free)
    float* sh = reinterpret_cast<float*>(smem + SM_A_BASE);   // [q][r][2] for q=1..3
    __syncthreads();
    if (q > 0) {
        sh[((q - 1) * 128 + r) * 2 + 0] = s0;
        sh[((q - 1) * 128 + r) * 2 + 1] = s1;
    }
    __syncthreads();
    if (q == 0 && grow < N_NODES) {
        float t0 = s0, t1 = s1;
#pragma unroll
        for (int u = 0; u < 3; u++) {
            t0 += sh[(u * 128 + r) * 2 + 0];
            t1 += sh[(u * 128 + r) * 2 + 1];
        }
        g_esrc[grow] = t0;
        g_etar[grow] = t1;
        float z = t0 + t1;
        float lz = z > 0.f ? z : NEG_SLOPE * z;
        g_eself[grow] = expf(lz);
    }

    __syncthreads();
    if (wid == 0 && lane == 0) {
        asm volatile("mbarrier.inval.shared.b64 [%0];" :: "r"(sbase + SM_MBAR) : "memory");
    }
    __syncthreads();
    if (wid == 0) {
        asm volatile("tcgen05.relinquish_alloc_permit.cta_group::1.sync.aligned;");
        asm volatile("tcgen05.dealloc.cta_group::1.sync.aligned.b32 %0, %1;"
                     :: "r"(tmem), "r"(128u));
    }
#else
    (void)x; (void)W; (void)b; (void)att;
#endif
}

// -------- fallback fp32 SGEMM + epre (compiled only for non-sm_103a SASS) ----
__global__ __launch_bounds__(256) void k_gemm_fp32(const float* __restrict__ x,
                                                   const float* __restrict__ W,
                                                   const float* __restrict__ b) {
#if !defined(__CUDA_ARCH_FEAT_SM103_ALL)
    __shared__ float xs[32][132];
    __shared__ float ws[32][132];

    const int tid = threadIdx.x;
    const int tx = tid & 15;
    const int ty = tid >> 4;
    const int row0 = blockIdx.x * 128;

    float acc[8][8];
#pragma unroll
    for (int i = 0; i < 8; i++)
#pragma unroll
        for (int j = 0; j < 8; j++) acc[i][j] = 0.f;

    for (int k0 = 0; k0 < IN_CH; k0 += 32) {
#pragma unroll
        for (int l = 0; l < 4; l++) {
            int idx = tid + l * 256;
            int r  = idx >> 3;
            int kq = idx & 7;
            int grow = row0 + r;
            float4 v = make_float4(0.f, 0.f, 0.f, 0.f);
            if (grow < N_NODES)
                v = *reinterpret_cast<const float4*>(&x[(size_t)grow * IN_CH + k0 + kq * 4]);
            xs[kq * 4 + 0][r] = v.x;
            xs[kq * 4 + 1][r] = v.y;
            xs[kq * 4 + 2][r] = v.z;
            xs[kq * 4 + 3][r] = v.w;
        }
#pragma unroll
        for (int l = 0; l < 4; l++) {
            int idx = tid + l * 256;
            int cc = idx >> 3;
            int kq = idx & 7;
            float4 v = *reinterpret_cast<const float4*>(&W[(size_t)cc * IN_CH + k0 + kq * 4]);
            ws[kq * 4 + 0][cc] = v.x;
            ws[kq * 4 + 1][cc] = v.y;
            ws[kq * 4 + 2][cc] = v.z;
            ws[kq * 4 + 3][cc] = v.w;
        }
        __syncthreads();

#pragma unroll
        for (int kk = 0; kk < 32; kk++) {
            float a[8], bb[8];
            float4 a0 = *reinterpret_cast<const float4*>(&xs[kk][ty * 8]);
            float4 a1 = *reinterpret_cast<const float4*>(&xs[kk][ty * 8 + 4]);
            float4 b0 = *reinterpret_cast<const float4*>(&ws[kk][tx * 8]);
            float4 b1 = *reinterpret_cast<const float4*>(&ws[kk][tx * 8 + 4]);
            a[0]=a0.x; a[1]=a0.y; a[2]=a0.z; a[3]=a0.w;
            a[4]=a1.x; a[5]=a1.y; a[6]=a1.z; a[7]=a1.w;
            bb[0]=b0.x; bb[1]=b0.y; bb[2]=b0.z; bb[3]=b0.w;
            bb[4]=b1.x; bb[5]=b1.y; bb[6]=b1.z; bb[7]=b1.w;
#pragma unroll
            for (int i = 0; i < 8; i++)
#pragma unroll
                for (int j = 0; j < 8; j++)
                    acc[i][j] = fmaf(a[i], bb[j], acc[i][j]);
        }
        __syncthreads();
    }

#pragma unroll
    for (int i = 0; i < 8; i++) {
        int grow = row0 + ty * 8 + i;
        if (grow >= N_NODES) break;
#pragma unroll
        for (int j = 0; j < 8; j += 4) {
            int col = tx * 8 + j;
            float4 bv = *reinterpret_cast<const float4*>(&b[col]);
            float4 o;
            o.x = acc[i][j + 0] + bv.x;
            o.y = acc[i][j + 1] + bv.y;
            o.z = acc[i][j + 2] + bv.z;
            o.w = acc[i][j + 3] + bv.w;
            *reinterpret_cast<float4*>(&g_feat[(size_t)grow * HC + col]) = o;
        }
    }
#else
    (void)x; (void)W; (void)b;
#endif
}

__global__ __launch_bounds__(256) void k_epre(const float* __restrict__ att) {
#if !defined(__CUDA_ARCH_FEAT_SM103_ALL)
    int warp = (blockIdx.x * blockDim.x + threadIdx.x) >> 5;
    if (warp >= N_NODES) return;
    int lane = threadIdx.x & 31;

    const float4* f4 = reinterpret_cast<const float4*>(g_feat);
    float4 f = f4[(size_t)warp * 32 + lane];
    float4 a0 = *reinterpret_cast<const float4*>(&att[lane * 8]);
    float4 a1 = *reinterpret_cast<const float4*>(&att[lane * 8 + 4]);

    float s0 = f.x * a0.x + f.y * a0.z + f.z * a1.x + f.w * a1.z;
    float s1 = f.x * a0.y + f.y * a0.w + f.z * a1.y + f.w * a1.w;
#pragma unroll
    for (int o = 16; o > 0; o >>= 1) {
        s0 += __shfl_xor_sync(0xffffffffu, s0, o);
        s1 += __shfl_xor_sync(0xffffffffu, s1, o);
    }
    if (lane == 0) {
        g_esrc[warp] = s0;
        g_etar[warp] = s1;
        float z = s0 + s1;
        float lz = z > 0.f ? z : NEG_SLOPE * z;
        g_eself[warp] = expf(lz);
    }
#else
    (void)att;
#endif
}

// ---------------- Kernel 3: histogram of destination nodes -------------------
__global__ __launch_bounds__(256) void k_hist(const void* __restrict__ ei) {
    int i = blockIdx.x * blockDim.x + threadIdx.x;
    if (i >= N_EDGES) return;
    int t, s;
    load_edge(ei, i, t, s);
    if ((unsigned)t >= N_NODES || (unsigned)s >= N_NODES) return;
    atomicAdd(&g_counts[t], 1);
}

// ---------------- Kernels 4a/4b/4c: multi-block exclusive scan ---------------
__global__ __launch_bounds__(1024) void k_scan1() {
    __shared__ int wsum[32];
    int i = blockIdx.x * 1024 + threadIdx.x;
    int lane = threadIdx.x & 31, wd = threadIdx.x >> 5;
    int v = (i < N_NODES) ? g_counts[i] : 0;
    int xv = v;
#pragma unroll
    for (int o = 1; o < 32; o <<= 1) {
        int y = __shfl_up_sync(0xffffffffu, xv, o);
        if (lane >= o) xv += y;
    }
    if (lane == 31) wsum[wd] = xv;
    __syncthreads();
    if (wd == 0) {
        int s = wsum[lane];
#pragma unroll
        for (int o = 1; o < 32; o <<= 1) {
            int y = __shfl_up_sync(0xffffffffu, s, o);
            if (lane >= o) s += y;
        }
        wsum[lane] = s;
    }
    __syncthreads();
    int base = (wd > 0) ? wsum[wd - 1] : 0;
    if (i < N_NODES) g_offsets[i] = base + xv - v;
    if (threadIdx.x == 1023) g_bsums[blockIdx.x] = wsum[31];
}

__global__ __launch_bounds__(128) void k_scan2(int nblocks) {
    __shared__ int sh[128];
    int t = threadIdx.x;
    int v = (t < nblocks) ? g_bsums[t] : 0;
    sh[t] = v;
    __syncthreads();
#pragma unroll
    for (int o = 1; o < 128; o <<= 1) {
        int y = (t >= o) ? sh[t - o] : 0;
        __syncthreads();
        sh[t] += y;
        __syncthreads();
    }
    if (t < nblocks) g_bsums[t] = sh[t] - v;
}

__global__ __launch_bounds__(256) void k_scan3() {
    int i = blockIdx.x * blockDim.x + threadIdx.x;
    if (i >= N_NODES) return;
    int off = g_offsets[i] + g_bsums[i >> 10];
    g_offsets[i] = off;
    g_cursor[i]  = off;
}

// ---------------- Kernel 5: scatter edge sources into CSR --------------------
__global__ __launch_bounds__(256) void k_scatter(const void* __restrict__ ei) {
    int i = blockIdx.x * blockDim.x + threadIdx.x;
    if (i >= N_EDGES) return;
    int t, s;
    load_edge(ei, i, t, s);
    if ((unsigned)t >= N_NODES || (unsigned)s >= N_NODES) return;
    int pos = atomicAdd(&g_cursor[t], 1);
    g_srcs[pos] = s;
}

// ---------------- Kernel 6: aggregation, one warp per node -------------------
__global__ __launch_bounds__(256) void k_agg(float* __restrict__ out) {
    int warp = (blockIdx.x * blockDim.x + threadIdx.x) >> 5;
    if (warp >= N_NODES) return;
    int lane = threadIdx.x & 31;

    const float4* f4 = reinterpret_cast<const float4*>(g_feat);
    int off = g_offsets[warp];
    int cnt = g_counts[warp];
    float etar = g_etar[warp];

    float4 acc = make_float4(0.f, 0.f, 0.f, 0.f);
    float sum_e = 0.f;
    int j = 0;
#pragma unroll 1
    for (; j + 4 <= cnt; j += 4) {
#pragma unroll
        for (int u = 0; u < 4; u++) {
            int s = g_srcs[off + j + u];
            float z = g_esrc[s] + etar;
            float lz = z > 0.f ? z : NEG_SLOPE * z;
            float e = expf(lz);
            sum_e += e;
            float4 f = f4[(size_t)s * 32 + lane];
            acc.x = fmaf(e, f.x, acc.x);
            acc.y = fmaf(e, f.y, acc.y);
            acc.z = fmaf(e, f.z, acc.z);
            acc.w = fmaf(e, f.w, acc.w);
        }
    }
    for (; j < cnt; j++) {
        int s = g_srcs[off + j];
        float z = g_esrc[s] + etar;
        float lz = z > 0.f ? z : NEG_SLOPE * z;
        float e = expf(lz);
        sum_e += e;
        float4 f = f4[(size_t)s * 32 + lane];
        acc.x = fmaf(e, f.x, acc.x);
        acc.y = fmaf(e, f.y, acc.y);
        acc.z = fmaf(e, f.z, acc.z);
        acc.w = fmaf(e, f.w, acc.w);
    }

    float es  = g_eself[warp];
    float inv = 1.0f / (sum_e + es);
    float4 fs = f4[(size_t)warp * 32 + lane];
    float4 o;
    o.x = (acc.x + es * fs.x) * inv;
    o.y = (acc.y + es * fs.y) * inv;
    o.z = (acc.z + es * fs.z) * inv;
    o.w = (acc.w + es * fs.w) * inv;
    reinterpret_cast<float4*>(out)[(size_t)warp * 32 + lane] = o;
}

// ---------------- launch ------------------------------------------------------
extern "C" void kernel_launch(void* const* d_in, const int* in_sizes, int n_in,
                              void* d_out, int out_size) {
    const float* x   = nullptr;
    const void*  ei  = nullptr;
    const float* W   = nullptr;
    const float* b   = nullptr;
    const float* att = nullptr;
    for (int i = 0; i < n_in; i++) {
        switch (in_sizes[i]) {
            case 25600000: x   = (const float*)d_in[i]; break;
            case 3200000:  ei  = d_in[i];               break;
            case 32768:    W   = (const float*)d_in[i]; break;
            case 128:      b   = (const float*)d_in[i]; break;
            case 256:      att = (const float*)d_in[i]; break;
            default: break;
        }
    }
    float* out = (float*)d_out;
    (void)out_size;

    int edge_blocks = (N_EDGES + 255) / 256;           // 6250
    int scan_blocks = (N_NODES + 1023) / 1024;         // 98
    int gemm_blocks = (N_NODES + 127) / 128;           // 782

    // Order chosen so launch #6 (ncu -s 5 -c 1) is k_gemm_tc5.
    k_detect<<<1, 32>>>((const long long*)ei);                 // 1
    k_zero<<<(N_NODES + 1023) / 1024, 1024>>>();               // 2
    k_hist<<<edge_blocks, 256>>>(ei);                          // 3
    k_scan1<<<scan_blocks, 1024>>>();                          // 4
    k_scan2<<<1, 128>>>(scan_blocks);                          // 5

    cudaFuncSetAttribute(k_gemm_tc5, cudaFuncAttributeMaxDynamicSharedMemorySize, SM_TOTAL);
    k_gemm_tc5<<<gemm_blocks, 512, SM_TOTAL>>>(x, W, b, att);  // 6  <- profiled

    k_scan3<<<(N_NODES + 255) / 256, 256>>>();                 // 7
    k_scatter<<<edge_blocks, 256>>>(ei);                       // 8
    k_gemm_fp32<<<gemm_blocks, 256>>>(x, W, b);                // 9 (no-op on 103a)
    k_epre<<<(N_NODES * 32 + 255) / 256, 256>>>(att);          // 10 (no-op on 103a)

    int node_warp_blocks = (N_NODES * 32 + 255) / 256;         // 12500
    k_agg<<<node_warp_blocks, 256>>>(out);                     // 11
}

// round 10
// speedup vs baseline: 2.5240x; 1.0599x over previous
#include <cuda_runtime.h>
#include <cuda_bf16.h>
#include <cstdint>

#define N_NODES 100000
#define N_EDGES 1600000
#define IN_CH   256
#define HC      128        // HEADS*OUT_CH
#define NEG_SLOPE 0.2f

// ---------------- scratch (static device globals; no allocation) -------------
__device__ __align__(16) float g_feat[(size_t)N_NODES * HC];   // 51.2 MB
__device__ float g_esrc[N_NODES];
__device__ float g_etar[N_NODES];
__device__ float g_eself[N_NODES];
__device__ int   g_counts[N_NODES];
__device__ int   g_offsets[N_NODES];
__device__ int   g_cursor[N_NODES];
__device__ int   g_bsums[128];
__device__ int   g_srcs[N_EDGES];
__device__ int   g_is32;

// ---------------- Kernel 0: sniff edge_index dtype ---------------------------
__global__ void k_detect(const long long* __restrict__ p) {
    if (blockIdx.x == 0 && threadIdx.x == 0) {
        int f = 0;
        for (int j = 0; j < 64; j++) {
            long long v = p[j];
            if (v < 0 || v >= (long long)N_NODES) f = 1;
        }
        g_is32 = f;
    }
}

// ---------------- Kernel 0b: zero per-node counts ----------------------------
__global__ __launch_bounds__(1024) void k_zero() {
    int i = blockIdx.x * 1024 + threadIdx.x;
    if (i < N_NODES) g_counts[i] = 0;
}

__device__ __forceinline__ void load_edge(const void* ei, int i, int& t, int& s) {
    if (g_is32) {
        const int* p = (const int*)ei;
        t = p[i];
        s = p[N_EDGES + i];
    } else {
        const long long* p = (const long long*)ei;
        t = (int)p[i];
        s = (int)p[N_EDGES + i];
    }
}

// ======================= tcgen05 GEMM (sm_103a builds only) ==================
#if defined(__CUDA_ARCH_FEAT_SM103_ALL)
__device__ __forceinline__ uint32_t smem_u32(const void* p) {
    uint32_t a;
    asm("{ .reg .u64 t; cvta.to.shared.u64 t, %1; cvt.u32.u64 %0, t; }" : "=r"(a) : "l"(p));
    return a;
}
__device__ __forceinline__ uint32_t elect_one() {
    uint32_t pred;
    asm volatile("{\n\t.reg .pred p;\n\telect.sync _|p, 0xFFFFFFFF;\n\tselp.b32 %0, 1, 0, p;\n\t}"
                 : "=r"(pred));
    return pred;
}
__device__ __forceinline__ uint64_t mk_desc(uint32_t addr) {
    return ((uint64_t)2 << 61) | ((uint64_t)1 << 46) | ((uint64_t)64 << 32) |
           ((uint64_t)1 << 16) | ((uint64_t)(addr >> 4) & 0x3FFF);
}
__device__ __forceinline__ void mma_f16_ss(uint32_t d_tmem, uint64_t a_desc,
                                           uint64_t b_desc, uint32_t idesc, uint32_t en) {
    asm volatile(
        "{\n\t.reg .pred p;\n\tsetp.ne.u32 p, %5, 0;\n\t"
        "tcgen05.mma.cta_group::1.kind::f16 [%0], %1, %2, %3, {%4, %4, %4, %4}, p;\n\t}"
        :: "r"(d_tmem), "l"(a_desc), "l"(b_desc), "r"(idesc), "r"(0u), "r"(en)
        : "memory");
}
__device__ __forceinline__ void mbar_wait(uint32_t mbar, uint32_t parity) {
    asm volatile(
        "{\n\t.reg .pred P1;\n\t"
        "WAIT_LOOP_%=:\n\t"
        "mbarrier.try_wait.parity.acquire.cta.shared::cta.b64 P1, [%0], %1, 0x989680;\n\t"
        "@P1 bra.uni WAIT_DONE_%=;\n\t"
        "bra.uni WAIT_LOOP_%=;\n\t"
        "WAIT_DONE_%=:\n\t}"
        :: "r"(mbar), "r"(parity) : "memory");
}
#endif

#define SWZ(x) ((x) ^ (((x) >> 3) & 0x70))
// idesc kind::f16: dtypeF32(b4) atypeBF16(b7) btypeBF16(b10) N/8<<17 M/16<<24
#define GEMM_IDESC ((1u<<4)|(1u<<7)|(1u<<10)|((HC/8)<<17)|((128/16)<<24))

#define SM_TMEMPTR 0
#define SM_MBAR    8
#define SM_W_HI    1024                    // 128 x 256 bf16 = 64KB
#define SM_W_LO    (SM_W_HI + 65536)
#define SM_A_BASE  (SM_W_LO + 65536)       // 2 buffers x (HI 16K + LO 16K)
#define SM_TOTAL   (SM_A_BASE + 2 * 32768) // 197632 B

// Block tile M=128 x N=128, K=256 in chunks of 64, double-buffered A. bf16x3.
// 512 threads: 16 warps for loads/convert/epilogue.
__global__ __launch_bounds__(512, 1)
void k_gemm_tc5(const float* __restrict__ x, const float* __restrict__ W,
                const float* __restrict__ b, const float* __restrict__ att) {
#if defined(__CUDA_ARCH_FEAT_SM103_ALL)
    extern __shared__ char smem[];
    const uint32_t sbase = smem_u32(smem);
    const int tid  = threadIdx.x;
    const int wid  = tid >> 5;
    const int lane = tid & 31;
    const int row0 = blockIdx.x * 128;

    if (wid == 0) {
        asm volatile("tcgen05.alloc.cta_group::1.sync.aligned.shared::cta.b32 [%0], %1;"
                     :: "r"(sbase + SM_TMEMPTR), "r"(128u) : "memory");
    }
    if (wid == 0 && lane == 0) {
        asm volatile("mbarrier.init.shared.b64 [%0], %1;"
                     :: "r"(sbase + SM_MBAR), "r"(1u) : "memory");
    }
    __syncthreads();
    uint32_t tmem;
    asm volatile("ld.shared.b32 %0, [%1];" : "=r"(tmem) : "r"(sbase + SM_TMEMPTR));

    // W (128n x 256k) -> SW128 blocked atoms, hi/lo bf16 planes (once per CTA).
    for (int g = tid; g < 4096; g += 512) {
        int row = g >> 5;
        int k   = (g & 31) * 8;
        float4 v0 = *reinterpret_cast<const float4*>(&W[(size_t)row * IN_CH + k]);
        float4 v1 = *reinterpret_cast<const float4*>(&W[(size_t)row * IN_CH + k + 4]);
        float f[8] = {v0.x, v0.y, v0.z, v0.w, v1.x, v1.y, v1.z, v1.w};
        __nv_bfloat16 hb[8], lb[8];
#pragma unroll
        for (int i = 0; i < 8; i++) {
            hb[i] = __float2bfloat16_rn(f[i]);
            lb[i] = __float2bfloat16_rn(f[i] - __bfloat162float(hb[i]));
        }
        uint32_t atom = (row >> 3) + (k >> 6) * 16;
        uint32_t byte = atom * 1024 + (row & 7) * 128 + (k & 63) * 2;
        uint32_t sw = SWZ(byte);
        *reinterpret_cast<uint4*>(smem + SM_W_HI + sw) = *reinterpret_cast<uint4*>(hb);
        *reinterpret_cast<uint4*>(smem + SM_W_LO + sw) = *reinterpret_cast<uint4*>(lb);
    }

    const uint64_t w_hi_d = mk_desc(sbase + SM_W_HI);
    const uint64_t w_lo_d = mk_desc(sbase + SM_W_LO);

    int nwaits = 0;

#pragma unroll 1
    for (int c = 0; c < 4; c++) {
        int buf = c & 1;
        uint32_t a_hi_off = SM_A_BASE + buf * 32768;
        uint32_t a_lo_off = a_hi_off + 16384;

        if (c >= 2) {              // free this buffer: chunk c-2's MMAs must be done
            mbar_wait(sbase + SM_MBAR, nwaits & 1);
            nwaits++;
        }

        // A chunk: 128 rows x 64 k -> hi/lo planes (16 atoms); 2 iters/thread
        for (int g = tid; g < 1024; g += 512) {
            int row = g >> 3;
            int k   = (g & 7) * 8;
            int grow = row0 + row;
            float f[8] = {0.f, 0.f, 0.f, 0.f, 0.f, 0.f, 0.f, 0.f};
            if (grow < N_NODES) {
                float4 v0 = *reinterpret_cast<const float4*>(&x[(size_t)grow * IN_CH + c * 64 + k]);
                float4 v1 = *reinterpret_cast<const float4*>(&x[(size_t)grow * IN_CH + c * 64 + k + 4]);
                f[0]=v0.x; f[1]=v0.y; f[2]=v0.z; f[3]=v0.w;
                f[4]=v1.x; f[5]=v1.y; f[6]=v1.z; f[7]=v1.w;
            }
            __nv_bfloat16 hb[8], lb[8];
#pragma unroll
            for (int i = 0; i < 8; i++) {
                hb[i] = __float2bfloat16_rn(f[i]);
                lb[i] = __float2bfloat16_rn(f[i] - __bfloat162float(hb[i]));
            }
            uint32_t byte = (row >> 3) * 1024 + (row & 7) * 128 + k * 2;
            uint32_t sw = SWZ(byte);
            *reinterpret_cast<uint4*>(smem + a_hi_off + sw) = *reinterpret_cast<uint4*>(hb);
            *reinterpret_cast<uint4*>(smem + a_lo_off + sw) = *reinterpret_cast<uint4*>(lb);
        }
        asm volatile("fence.proxy.async.shared::cta;" ::: "memory");
        __syncthreads();

        if (wid == 0 && elect_one()) {
            uint64_t a_hi_d = mk_desc(sbase + a_hi_off);
            uint64_t a_lo_d = mk_desc(sbase + a_lo_off);
            uint64_t wbase_hi = w_hi_d + (uint64_t)c * 1024;   // 16 atoms/chunk
            uint64_t wbase_lo = w_lo_d + (uint64_t)c * 1024;
#pragma unroll
            for (int ks = 0; ks < 4; ks++) {                    // K=16 per mma
                uint64_t ah = a_hi_d + ks * 2;
                uint64_t al = a_lo_d + ks * 2;
                uint64_t bh = wbase_hi + ks * 2;
                uint64_t bl = wbase_lo + ks * 2;
                uint32_t en0 = (c == 0 && ks == 0) ? 0u : 1u;
                mma_f16_ss(tmem, ah, bh, GEMM_IDESC, en0);
                mma_f16_ss(tmem, al, bh, GEMM_IDESC, 1u);
                mma_f16_ss(tmem, ah, bl, GEMM_IDESC, 1u);
            }
            asm volatile(
                "tcgen05.commit.cta_group::1.mbarrier::arrive::one.shared::cluster.b64 [%0];"
                :: "r"(sbase + SM_MBAR) : "memory");
        }
        __syncthreads();
    }

    // drain remaining commits (chunks 2 and 3)
    mbar_wait(sbase + SM_MBAR, nwaits & 1); nwaits++;
    mbar_wait(sbase + SM_MBAR, nwaits & 1); nwaits++;
    asm volatile("tcgen05.fence::after_thread_sync;" ::: "memory");

    // epilogue: 16 warps. Subpartition (row group) = wid&3 (HW-forced for LDTM),
    // column quarter = wid>>2. One LDTM x32 per warp (32 cols x 32 rows).
    int rg   = wid & 3;
    int q    = wid >> 2;          // 0..3
    int r    = rg * 32 + lane;
    int grow = row0 + r;
    int c0   = q * 32;
    float s0 = 0.f, s1 = 0.f;
    {
        uint32_t d[32];
        asm volatile(
            "tcgen05.ld.sync.aligned.32x32b.x32.b32 "
            "{%0,%1,%2,%3,%4,%5,%6,%7,%8,%9,%10,%11,%12,%13,%14,%15,"
            "%16,%17,%18,%19,%20,%21,%22,%23,%24,%25,%26,%27,%28,%29,%30,%31}, [%32];"
            : "=r"(d[0]),"=r"(d[1]),"=r"(d[2]),"=r"(d[3]),"=r"(d[4]),"=r"(d[5]),"=r"(d[6]),"=r"(d[7]),
              "=r"(d[8]),"=r"(d[9]),"=r"(d[10]),"=r"(d[11]),"=r"(d[12]),"=r"(d[13]),"=r"(d[14]),"=r"(d[15]),
              "=r"(d[16]),"=r"(d[17]),"=r"(d[18]),"=r"(d[19]),"=r"(d[20]),"=r"(d[21]),"=r"(d[22]),"=r"(d[23]),
              "=r"(d[24]),"=r"(d[25]),"=r"(d[26]),"=r"(d[27]),"=r"(d[28]),"=r"(d[29]),"=r"(d[30]),"=r"(d[31])
            : "r"(tmem + c0));
        asm volatile("tcgen05.wait::ld.sync.aligned;" ::: "memory");
        if (grow < N_NODES) {
#pragma unroll
            for (int qq = 0; qq < 32; qq += 4) {
                float4 bv = *reinterpret_cast<const float4*>(&b[c0 + qq]);
                float4 o;
                o.x = __uint_as_float(d[qq + 0]) + bv.x;
                o.y = __uint_as_float(d[qq + 1]) + bv.y;
                o.z = __uint_as_float(d[qq + 2]) + bv.z;
                o.w = __uint_as_float(d[qq + 3]) + bv.w;
                *reinterpret_cast<float4*>(&g_feat[(size_t)grow * HC + c0 + qq]) = o;
                const float* ov = reinterpret_cast<const float*>(&o);
#pragma unroll
                for (int i = 0; i < 4; i++) {
                    int col = c0 + qq + i;
                    s0 = fmaf(ov[i], att[2 * col],     s0);
                    s1 = fmaf(ov[i], att[2 * col + 1], s1);
                }
            }
        }
    }

    // reduce att-dot partials across the 4 quarter-warps per row (A bufs free)
    float* sh = reinterpret_cast<float*>(smem + SM_A_BASE);   // [q][r][2] for q=1..3
    __syncthreads();
    if (q > 0) {
        sh[((q - 1) * 128 + r) * 2 + 0] = s0;
        sh[((q - 1) * 128 + r) * 2 + 1] = s1;
    }
    __syncthreads();
    if (q == 0 && grow < N_NODES) {
        float t0 = s0, t1 = s1;
#pragma unroll
        for (int u = 0; u < 3; u++) {
            t0 += sh[(u * 128 + r) * 2 + 0];
            t1 += sh[(u * 128 + r) * 2 + 1];
        }
        g_esrc[grow] = t0;
        g_etar[grow] = t1;
        float z = t0 + t1;
        float lz = z > 0.f ? z : NEG_SLOPE * z;
        g_eself[grow] = expf(lz);
    }

    __syncthreads();
    if (wid == 0 && lane == 0) {
        asm volatile("mbarrier.inval.shared.b64 [%0];" :: "r"(sbase + SM_MBAR) : "memory");
    }
    __syncthreads();
    if (wid == 0) {
        asm volatile("tcgen05.relinquish_alloc_permit.cta_group::1.sync.aligned;");
        asm volatile("tcgen05.dealloc.cta_group::1.sync.aligned.b32 %0, %1;"
                     :: "r"(tmem), "r"(128u));
    }
#else
    (void)x; (void)W; (void)b; (void)att;
#endif
}

// -------- fallback fp32 SGEMM + epre (compiled only for non-sm_103a SASS) ----
__global__ __launch_bounds__(256) void k_gemm_fp32(const float* __restrict__ x,
                                                   const float* __restrict__ W,
                                                   const float* __restrict__ b) {
#if !defined(__CUDA_ARCH_FEAT_SM103_ALL)
    __shared__ float xs[32][132];
    __shared__ float ws[32][132];

    const int tid = threadIdx.x;
    const int tx = tid & 15;
    const int ty = tid >> 4;
    const int row0 = blockIdx.x * 128;

    float acc[8][8];
#pragma unroll
    for (int i = 0; i < 8; i++)
#pragma unroll
        for (int j = 0; j < 8; j++) acc[i][j] = 0.f;

    for (int k0 = 0; k0 < IN_CH; k0 += 32) {
#pragma unroll
        for (int l = 0; l < 4; l++) {
            int idx = tid + l * 256;
            int r  = idx >> 3;
            int kq = idx & 7;
            int grow = row0 + r;
            float4 v = make_float4(0.f, 0.f, 0.f, 0.f);
            if (grow < N_NODES)
                v = *reinterpret_cast<const float4*>(&x[(size_t)grow * IN_CH + k0 + kq * 4]);
            xs[kq * 4 + 0][r] = v.x;
            xs[kq * 4 + 1][r] = v.y;
            xs[kq * 4 + 2][r] = v.z;
            xs[kq * 4 + 3][r] = v.w;
        }
#pragma unroll
        for (int l = 0; l < 4; l++) {
            int idx = tid + l * 256;
            int cc = idx >> 3;
            int kq = idx & 7;
            float4 v = *reinterpret_cast<const float4*>(&W[(size_t)cc * IN_CH + k0 + kq * 4]);
            ws[kq * 4 + 0][cc] = v.x;
            ws[kq * 4 + 1][cc] = v.y;
            ws[kq * 4 + 2][cc] = v.z;
            ws[kq * 4 + 3][cc] = v.w;
        }
        __syncthreads();

#pragma unroll
        for (int kk = 0; kk < 32; kk++) {
            float a[8], bb[8];
            float4 a0 = *reinterpret_cast<const float4*>(&xs[kk][ty * 8]);
            float4 a1 = *reinterpret_cast<const float4*>(&xs[kk][ty * 8 + 4]);
            float4 b0 = *reinterpret_cast<const float4*>(&ws[kk][tx * 8]);
            float4 b1 = *reinterpret_cast<const float4*>(&ws[kk][tx * 8 + 4]);
            a[0]=a0.x; a[1]=a0.y; a[2]=a0.z; a[3]=a0.w;
            a[4]=a1.x; a[5]=a1.y; a[6]=a1.z; a[7]=a1.w;
            bb[0]=b0.x; bb[1]=b0.y; bb[2]=b0.z; bb[3]=b0.w;
            bb[4]=b1.x; bb[5]=b1.y; bb[6]=b1.z; bb[7]=b1.w;
#pragma unroll
            for (int i = 0; i < 8; i++)
#pragma unroll
                for (int j = 0; j < 8; j++)
                    acc[i][j] = fmaf(a[i], bb[j], acc[i][j]);
        }
        __syncthreads();
    }

#pragma unroll
    for (int i = 0; i < 8; i++) {
        int grow = row0 + ty * 8 + i;
        if (grow >= N_NODES) break;
#pragma unroll
        for (int j = 0; j < 8; j += 4) {
            int col = tx * 8 + j;
            float4 bv = *reinterpret_cast<const float4*>(&b[col]);
            float4 o;
            o.x = acc[i][j + 0] + bv.x;
            o.y = acc[i][j + 1] + bv.y;
            o.z = acc[i][j + 2] + bv.z;
            o.w = acc[i][j + 3] + bv.w;
            *reinterpret_cast<float4*>(&g_feat[(size_t)grow * HC + col]) = o;
        }
    }
#else
    (void)x; (void)W; (void)b;
#endif
}

__global__ __launch_bounds__(256) void k_epre(const float* __restrict__ att) {
#if !defined(__CUDA_ARCH_FEAT_SM103_ALL)
    int warp = (blockIdx.x * blockDim.x + threadIdx.x) >> 5;
    if (warp >= N_NODES) return;
    int lane = threadIdx.x & 31;

    const float4* f4 = reinterpret_cast<const float4*>(g_feat);
    float4 f = f4[(size_t)warp * 32 + lane];
    float4 a0 = *reinterpret_cast<const float4*>(&att[lane * 8]);
    float4 a1 = *reinterpret_cast<const float4*>(&att[lane * 8 + 4]);

    float s0 = f.x * a0.x + f.y * a0.z + f.z * a1.x + f.w * a1.z;
    float s1 = f.x * a0.y + f.y * a0.w + f.z * a1.y + f.w * a1.w;
#pragma unroll
    for (int o = 16; o > 0; o >>= 1) {
        s0 += __shfl_xor_sync(0xffffffffu, s0, o);
        s1 += __shfl_xor_sync(0xffffffffu, s1, o);
    }
    if (lane == 0) {
        g_esrc[warp] = s0;
        g_etar[warp] = s1;
        float z = s0 + s1;
        float lz = z > 0.f ? z : NEG_SLOPE * z;
        g_eself[warp] = expf(lz);
    }
#else
    (void)att;
#endif
}

// ---------------- Kernel 3: histogram of destination nodes -------------------
__global__ __launch_bounds__(256) void k_hist(const void* __restrict__ ei) {
    int i = blockIdx.x * blockDim.x + threadIdx.x;
    if (i >= N_EDGES) return;
    int t, s;
    load_edge(ei, i, t, s);
    if ((unsigned)t >= N_NODES || (unsigned)s >= N_NODES) return;
    atomicAdd(&g_counts[t], 1);
}

// ---------------- Kernels 4a/4b/4c: multi-block exclusive scan ---------------
__global__ __launch_bounds__(1024) void k_scan1() {
    __shared__ int wsum[32];
    int i = blockIdx.x * 1024 + threadIdx.x;
    int lane = threadIdx.x & 31, wd = threadIdx.x >> 5;
    int v = (i < N_NODES) ? g_counts[i] : 0;
    int xv = v;
#pragma unroll
    for (int o = 1; o < 32; o <<= 1) {
        int y = __shfl_up_sync(0xffffffffu, xv, o);
        if (lane >= o) xv += y;
    }
    if (lane == 31) wsum[wd] = xv;
    __syncthreads();
    if (wd == 0) {
        int s = wsum[lane];
#pragma unroll
        for (int o = 1; o < 32; o <<= 1) {
            int y = __shfl_up_sync(0xffffffffu, s, o);
            if (lane >= o) s += y;
        }
        wsum[lane] = s;
    }
    __syncthreads();
    int base = (wd > 0) ? wsum[wd - 1] : 0;
    if (i < N_NODES) g_offsets[i] = base + xv - v;
    if (threadIdx.x == 1023) g_bsums[blockIdx.x] = wsum[31];
}

__global__ __launch_bounds__(128) void k_scan2(int nblocks) {
    __shared__ int sh[128];
    int t = threadIdx.x;
    int v = (t < nblocks) ? g_bsums[t] : 0;
    sh[t] = v;
    __syncthreads();
#pragma unroll
    for (int o = 1; o < 128; o <<= 1) {
        int y = (t >= o) ? sh[t - o] : 0;
        __syncthreads();
        sh[t] += y;
        __syncthreads();
    }
    if (t < nblocks) g_bsums[t] = sh[t] - v;
}

__global__ __launch_bounds__(256) void k_scan3() {
    int i = blockIdx.x * blockDim.x + threadIdx.x;
    if (i >= N_NODES) return;
    int off = g_offsets[i] + g_bsums[i >> 10];
    g_offsets[i] = off;
    g_cursor[i]  = off;
}

// ---------------- Kernel 5: scatter edge sources into CSR --------------------
// Single-wave grid (4 blocks/SM, zero smem) so the PDL trigger fires at kernel
// start and leaves room for one GEMM CTA (512 thr + 197KB smem) per SM.
__global__ __launch_bounds__(256) void k_scatter(const void* __restrict__ ei) {
#if __CUDA_ARCH__ >= 900
    cudaTriggerProgrammaticLaunchCompletion();
#endif
    int stride = gridDim.x * blockDim.x;
    for (int i = blockIdx.x * blockDim.x + threadIdx.x; i < N_EDGES; i += stride) {
        int t, s;
        load_edge(ei, i, t, s);
        if ((unsigned)t >= N_NODES || (unsigned)s >= N_NODES) continue;
        int pos = atomicAdd(&g_cursor[t], 1);
        g_srcs[pos] = s;
    }
}

// ---------------- Kernel 6: aggregation, one warp per node -------------------
__global__ __launch_bounds__(256) void k_agg(float* __restrict__ out) {
    int warp = (blockIdx.x * blockDim.x + threadIdx.x) >> 5;
    if (warp >= N_NODES) return;
    int lane = threadIdx.x & 31;

    const float4* f4 = reinterpret_cast<const float4*>(g_feat);
    int off = g_offsets[warp];
    int cnt = g_counts[warp];
    float etar = g_etar[warp];

    float4 acc = make_float4(0.f, 0.f, 0.f, 0.f);
    float sum_e = 0.f;
    int j = 0;
#pragma unroll 1
    for (; j + 4 <= cnt; j += 4) {
#pragma unroll
        for (int u = 0; u < 4; u++) {
            int s = g_srcs[off + j + u];
            float z = g_esrc[s] + etar;
            float lz = z > 0.f ? z : NEG_SLOPE * z;
            float e = expf(lz);
            sum_e += e;
            float4 f = f4[(size_t)s * 32 + lane];
            acc.x = fmaf(e, f.x, acc.x);
            acc.y = fmaf(e, f.y, acc.y);
            acc.z = fmaf(e, f.z, acc.z);
            acc.w = fmaf(e, f.w, acc.w);
        }
    }
    for (; j < cnt; j++) {
        int s = g_srcs[off + j];
        float z = g_esrc[s] + etar;
        float lz = z > 0.f ? z : NEG_SLOPE * z;
        float e = expf(lz);
        sum_e += e;
        float4 f = f4[(size_t)s * 32 + lane];
        acc.x = fmaf(e, f.x, acc.x);
        acc.y = fmaf(e, f.y, acc.y);
        acc.z = fmaf(e, f.z, acc.z);
        acc.w = fmaf(e, f.w, acc.w);
    }

    float es  = g_eself[warp];
    float inv = 1.0f / (sum_e + es);
    float4 fs = f4[(size_t)warp * 32 + lane];
    float4 o;
    o.x = (acc.x + es * fs.x) * inv;
    o.y = (acc.y + es * fs.y) * inv;
    o.z = (acc.z + es * fs.z) * inv;
    o.w = (acc.w + es * fs.w) * inv;
    reinterpret_cast<float4*>(out)[(size_t)warp * 32 + lane] = o;
}

// ---------------- launch ------------------------------------------------------
extern "C" void kernel_launch(void* const* d_in, const int* in_sizes, int n_in,
                              void* d_out, int out_size) {
    const float* x   = nullptr;
    const void*  ei  = nullptr;
    const float* W   = nullptr;
    const float* b   = nullptr;
    const float* att = nullptr;
    for (int i = 0; i < n_in; i++) {
        switch (in_sizes[i]) {
            case 25600000: x   = (const float*)d_in[i]; break;
            case 3200000:  ei  = d_in[i];               break;
            case 32768:    W   = (const float*)d_in[i]; break;
            case 128:      b   = (const float*)d_in[i]; break;
            case 256:      att = (const float*)d_in[i]; break;
            default: break;
        }
    }
    float* out = (float*)d_out;
    (void)out_size;

    int edge_blocks = (N_EDGES + 255) / 256;           // 6250
    int scan_blocks = (N_NODES + 1023) / 1024;         // 98
    int gemm_blocks = (N_NODES + 127) / 128;           // 782

    // CSR chain first (independent of GEMM), then GEMM overlapped with scatter
    // via PDL: scatter triggers at entry, GEMM launch waits only on that.
    k_detect<<<1, 32>>>((const long long*)ei);
    k_zero<<<(N_NODES + 1023) / 1024, 1024>>>();
    k_hist<<<edge_blocks, 256>>>(ei);
    k_scan1<<<scan_blocks, 1024>>>();
    k_scan2<<<1, 128>>>(scan_blocks);
    k_scan3<<<(N_NODES + 255) / 256, 256>>>();
    k_scatter<<<592, 256>>>(ei);      // single wave (4 blocks/SM), triggers PDL

    cudaFuncSetAttribute(k_gemm_tc5, cudaFuncAttributeMaxDynamicSharedMemorySize, SM_TOTAL);
    {
        cudaLaunchConfig_t cfg = {};
        cfg.gridDim  = dim3(gemm_blocks);
        cfg.blockDim = dim3(512);
        cfg.dynamicSmemBytes = SM_TOTAL;
        cfg.stream = 0;
        cudaLaunchAttribute attrs[1];
        attrs[0].id = cudaLaunchAttributeProgrammaticStreamSerialization;
        attrs[0].val.programmaticStreamSerializationAllowed = 1;
        cfg.attrs = attrs;
        cfg.numAttrs = 1;
        cudaLaunchKernelEx(&cfg, k_gemm_tc5, x, W, b, att);
    }

    k_gemm_fp32<<<gemm_blocks, 256>>>(x, W, b);                // no-op on 103a
    k_epre<<<(N_NODES * 32 + 255) / 256, 256>>>(att);          // no-op on 103a

    int node_warp_blocks = (N_NODES * 32 + 255) / 256;         // 12500
    k_agg<<<node_warp_blocks, 256>>>(out);
}

// round 11
// speedup vs baseline: 2.6597x; 1.0538x over previous
#include <cuda_runtime.h>
#include <cuda_bf16.h>
#include <cstdint>

#define N_NODES 100000
#define N_EDGES 1600000
#define IN_CH   256
#define HC      128        // HEADS*OUT_CH
#define NEG_SLOPE 0.2f

// ---------------- scratch (static device globals; no allocation) -------------
__device__ __align__(16) float g_feat[(size_t)N_NODES * HC];   // 51.2 MB
__device__ float g_esrc[N_NODES];
__device__ float g_etar[N_NODES];
__device__ float g_eself[N_NODES];
__device__ int   g_counts[N_NODES];
__device__ int   g_offsets[N_NODES];
__device__ int   g_cursor[N_NODES];
__device__ int   g_bsums[128];
__device__ int   g_srcs[N_EDGES];
__device__ int   g_is32;

// ---------------- Kernel 0: zero counts + fused dtype sniff ------------------
__global__ __launch_bounds__(1024) void k_zero(const long long* __restrict__ p) {
    int i = blockIdx.x * 1024 + threadIdx.x;
    if (i < N_NODES) g_counts[i] = 0;
    if (blockIdx.x == 0 && threadIdx.x == 0) {
        int f = 0;
        for (int j = 0; j < 64; j++) {
            long long v = p[j];
            if (v < 0 || v >= (long long)N_NODES) f = 1;
        }
        g_is32 = f;
    }
}

// ======================= tcgen05 GEMM (sm_103a builds only) ==================
#if defined(__CUDA_ARCH_FEAT_SM103_ALL)
__device__ __forceinline__ uint32_t smem_u32(const void* p) {
    uint32_t a;
    asm("{ .reg .u64 t; cvta.to.shared.u64 t, %1; cvt.u32.u64 %0, t; }" : "=r"(a) : "l"(p));
    return a;
}
__device__ __forceinline__ uint32_t elect_one() {
    uint32_t pred;
    asm volatile("{\n\t.reg .pred p;\n\telect.sync _|p, 0xFFFFFFFF;\n\tselp.b32 %0, 1, 0, p;\n\t}"
                 : "=r"(pred));
    return pred;
}
__device__ __forceinline__ uint64_t mk_desc(uint32_t addr) {
    return ((uint64_t)2 << 61) | ((uint64_t)1 << 46) | ((uint64_t)64 << 32) |
           ((uint64_t)1 << 16) | ((uint64_t)(addr >> 4) & 0x3FFF);
}
__device__ __forceinline__ void mma_f16_ss(uint32_t d_tmem, uint64_t a_desc,
                                           uint64_t b_desc, uint32_t idesc, uint32_t en) {
    asm volatile(
        "{\n\t.reg .pred p;\n\tsetp.ne.u32 p, %5, 0;\n\t"
        "tcgen05.mma.cta_group::1.kind::f16 [%0], %1, %2, %3, {%4, %4, %4, %4}, p;\n\t}"
        :: "r"(d_tmem), "l"(a_desc), "l"(b_desc), "r"(idesc), "r"(0u), "r"(en)
        : "memory");
}
__device__ __forceinline__ void mbar_wait(uint32_t mbar, uint32_t parity) {
    asm volatile(
        "{\n\t.reg .pred P1;\n\t"
        "WAIT_LOOP_%=:\n\t"
        "mbarrier.try_wait.parity.acquire.cta.shared::cta.b64 P1, [%0], %1, 0x989680;\n\t"
        "@P1 bra.uni WAIT_DONE_%=;\n\t"
        "bra.uni WAIT_LOOP_%=;\n\t"
        "WAIT_DONE_%=:\n\t}"
        :: "r"(mbar), "r"(parity) : "memory");
}
#endif

#define SWZ(x) ((x) ^ (((x) >> 3) & 0x70))
// idesc kind::f16: dtypeF32(b4) atypeBF16(b7) btypeBF16(b10) N/8<<17 M/16<<24
#define GEMM_IDESC ((1u<<4)|(1u<<7)|(1u<<10)|((HC/8)<<17)|((128/16)<<24))

#define SM_TMEMPTR 0
#define SM_MBAR    8
#define SM_W_HI    1024                    // 128 x 256 bf16 = 64KB
#define SM_W_LO    (SM_W_HI + 65536)
#define SM_A_BASE  (SM_W_LO + 65536)       // 2 buffers x (HI 16K + LO 16K)
#define SM_TOTAL   (SM_A_BASE + 2 * 32768) // 197632 B

// Block tile M=128 x N=128, K=256 in chunks of 64, double-buffered A. bf16x3.
// 512 threads: 16 warps for loads/convert/epilogue.
__global__ __launch_bounds__(512, 1)
void k_gemm_tc5(const float* __restrict__ x, const float* __restrict__ W,
                const float* __restrict__ b, const float* __restrict__ att) {
#if defined(__CUDA_ARCH_FEAT_SM103_ALL)
    extern __shared__ char smem[];
    const uint32_t sbase = smem_u32(smem);
    const int tid  = threadIdx.x;
    const int wid  = tid >> 5;
    const int lane = tid & 31;
    const int row0 = blockIdx.x * 128;

    if (wid == 0) {
        asm volatile("tcgen05.alloc.cta_group::1.sync.aligned.shared::cta.b32 [%0], %1;"
                     :: "r"(sbase + SM_TMEMPTR), "r"(128u) : "memory");
    }
    if (wid == 0 && lane == 0) {
        asm volatile("mbarrier.init.shared.b64 [%0], %1;"
                     :: "r"(sbase + SM_MBAR), "r"(1u) : "memory");
    }
    __syncthreads();
    uint32_t tmem;
    asm volatile("ld.shared.b32 %0, [%1];" : "=r"(tmem) : "r"(sbase + SM_TMEMPTR));

    // W (128n x 256k) -> SW128 blocked atoms, hi/lo bf16 planes (once per CTA).
    for (int g = tid; g < 4096; g += 512) {
        int row = g >> 5;
        int k   = (g & 31) * 8;
        float4 v0 = *reinterpret_cast<const float4*>(&W[(size_t)row * IN_CH + k]);
        float4 v1 = *reinterpret_cast<const float4*>(&W[(size_t)row * IN_CH + k + 4]);
        float f[8] = {v0.x, v0.y, v0.z, v0.w, v1.x, v1.y, v1.z, v1.w};
        __nv_bfloat16 hb[8], lb[8];
#pragma unroll
        for (int i = 0; i < 8; i++) {
            hb[i] = __float2bfloat16_rn(f[i]);
            lb[i] = __float2bfloat16_rn(f[i] - __bfloat162float(hb[i]));
        }
        uint32_t atom = (row >> 3) + (k >> 6) * 16;
        uint32_t byte = atom * 1024 + (row & 7) * 128 + (k & 63) * 2;
        uint32_t sw = SWZ(byte);
        *reinterpret_cast<uint4*>(smem + SM_W_HI + sw) = *reinterpret_cast<uint4*>(hb);
        *reinterpret_cast<uint4*>(smem + SM_W_LO + sw) = *reinterpret_cast<uint4*>(lb);
    }

    const uint64_t w_hi_d = mk_desc(sbase + SM_W_HI);
    const uint64_t w_lo_d = mk_desc(sbase + SM_W_LO);

    int nwaits = 0;

#pragma unroll 1
    for (int c = 0; c < 4; c++) {
        int buf = c & 1;
        uint32_t a_hi_off = SM_A_BASE + buf * 32768;
        uint32_t a_lo_off = a_hi_off + 16384;

        if (c >= 2) {              // free this buffer: chunk c-2's MMAs must be done
            mbar_wait(sbase + SM_MBAR, nwaits & 1);
            nwaits++;
        }

        // A chunk: 128 rows x 64 k -> hi/lo planes (16 atoms); 2 iters/thread
        for (int g = tid; g < 1024; g += 512) {
            int row = g >> 3;
            int k   = (g & 7) * 8;
            int grow = row0 + row;
            float f[8] = {0.f, 0.f, 0.f, 0.f, 0.f, 0.f, 0.f, 0.f};
            if (grow < N_NODES) {
                float4 v0 = *reinterpret_cast<const float4*>(&x[(size_t)grow * IN_CH + c * 64 + k]);
                float4 v1 = *reinterpret_cast<const float4*>(&x[(size_t)grow * IN_CH + c * 64 + k + 4]);
                f[0]=v0.x; f[1]=v0.y; f[2]=v0.z; f[3]=v0.w;
                f[4]=v1.x; f[5]=v1.y; f[6]=v1.z; f[7]=v1.w;
            }
            __nv_bfloat16 hb[8], lb[8];
#pragma unroll
            for (int i = 0; i < 8; i++) {
                hb[i] = __float2bfloat16_rn(f[i]);
                lb[i] = __float2bfloat16_rn(f[i] - __bfloat162float(hb[i]));
            }
            uint32_t byte = (row >> 3) * 1024 + (row & 7) * 128 + k * 2;
            uint32_t sw = SWZ(byte);
            *reinterpret_cast<uint4*>(smem + a_hi_off + sw) = *reinterpret_cast<uint4*>(hb);
            *reinterpret_cast<uint4*>(smem + a_lo_off + sw) = *reinterpret_cast<uint4*>(lb);
        }
        asm volatile("fence.proxy.async.shared::cta;" ::: "memory");
        __syncthreads();

        if (wid == 0 && elect_one()) {
            uint64_t a_hi_d = mk_desc(sbase + a_hi_off);
            uint64_t a_lo_d = mk_desc(sbase + a_lo_off);
            uint64_t wbase_hi = w_hi_d + (uint64_t)c * 1024;   // 16 atoms/chunk
            uint64_t wbase_lo = w_lo_d + (uint64_t)c * 1024;
#pragma unroll
            for (int ks = 0; ks < 4; ks++) {                    // K=16 per mma
                uint64_t ah = a_hi_d + ks * 2;
                uint64_t al = a_lo_d + ks * 2;
                uint64_t bh = wbase_hi + ks * 2;
                uint64_t bl = wbase_lo + ks * 2;
                uint32_t en0 = (c == 0 && ks == 0) ? 0u : 1u;
                mma_f16_ss(tmem, ah, bh, GEMM_IDESC, en0);
                mma_f16_ss(tmem, al, bh, GEMM_IDESC, 1u);
                mma_f16_ss(tmem, ah, bl, GEMM_IDESC, 1u);
            }
            asm volatile(
                "tcgen05.commit.cta_group::1.mbarrier::arrive::one.shared::cluster.b64 [%0];"
                :: "r"(sbase + SM_MBAR) : "memory");
        }
        __syncthreads();
    }

    // drain remaining commits (chunks 2 and 3)
    mbar_wait(sbase + SM_MBAR, nwaits & 1); nwaits++;
    mbar_wait(sbase + SM_MBAR, nwaits & 1); nwaits++;
    asm volatile("tcgen05.fence::after_thread_sync;" ::: "memory");

    // epilogue: 16 warps. Subpartition (row group) = wid&3 (HW-forced for LDTM),
    // column quarter = wid>>2. One LDTM x32 per warp (32 cols x 32 rows).
    int rg   = wid & 3;
    int q    = wid >> 2;          // 0..3
    int r    = rg * 32 + lane;
    int grow = row0 + r;
    int c0   = q * 32;
    float s0 = 0.f, s1 = 0.f;
    {
        uint32_t d[32];
        asm volatile(
            "tcgen05.ld.sync.aligned.32x32b.x32.b32 "
            "{%0,%1,%2,%3,%4,%5,%6,%7,%8,%9,%10,%11,%12,%13,%14,%15,"
            "%16,%17,%18,%19,%20,%21,%22,%23,%24,%25,%26,%27,%28,%29,%30,%31}, [%32];"
            : "=r"(d[0]),"=r"(d[1]),"=r"(d[2]),"=r"(d[3]),"=r"(d[4]),"=r"(d[5]),"=r"(d[6]),"=r"(d[7]),
              "=r"(d[8]),"=r"(d[9]),"=r"(d[10]),"=r"(d[11]),"=r"(d[12]),"=r"(d[13]),"=r"(d[14]),"=r"(d[15]),
              "=r"(d[16]),"=r"(d[17]),"=r"(d[18]),"=r"(d[19]),"=r"(d[20]),"=r"(d[21]),"=r"(d[22]),"=r"(d[23]),
              "=r"(d[24]),"=r"(d[25]),"=r"(d[26]),"=r"(d[27]),"=r"(d[28]),"=r"(d[29]),"=r"(d[30]),"=r"(d[31])
            : "r"(tmem + c0));
        asm volatile("tcgen05.wait::ld.sync.aligned;" ::: "memory");
        if (grow < N_NODES) {
#pragma unroll
            for (int qq = 0; qq < 32; qq += 4) {
                float4 bv = *reinterpret_cast<const float4*>(&b[c0 + qq]);
                float4 o;
                o.x = __uint_as_float(d[qq + 0]) + bv.x;
                o.y = __uint_as_float(d[qq + 1]) + bv.y;
                o.z = __uint_as_float(d[qq + 2]) + bv.z;
                o.w = __uint_as_float(d[qq + 3]) + bv.w;
                *reinterpret_cast<float4*>(&g_feat[(size_t)grow * HC + c0 + qq]) = o;
                const float* ov = reinterpret_cast<const float*>(&o);
#pragma unroll
                for (int i = 0; i < 4; i++) {
                    int col = c0 + qq + i;
                    s0 = fmaf(ov[i], att[2 * col],     s0);
                    s1 = fmaf(ov[i], att[2 * col + 1], s1);
                }
            }
        }
    }

    // reduce att-dot partials across the 4 quarter-warps per row (A bufs free)
    float* sh = reinterpret_cast<float*>(smem + SM_A_BASE);   // [q][r][2] for q=1..3
    __syncthreads();
    if (q > 0) {
        sh[((q - 1) * 128 + r) * 2 + 0] = s0;
        sh[((q - 1) * 128 + r) * 2 + 1] = s1;
    }
    __syncthreads();
    if (q == 0 && grow < N_NODES) {
        float t0 = s0, t1 = s1;
#pragma unroll
        for (int u = 0; u < 3; u++) {
            t0 += sh[(u * 128 + r) * 2 + 0];
            t1 += sh[(u * 128 + r) * 2 + 1];
        }
        g_esrc[grow] = t0;
        g_etar[grow] = t1;
        float z = t0 + t1;
        float lz = z > 0.f ? z : NEG_SLOPE * z;
        g_eself[grow] = expf(lz);
    }

    __syncthreads();
    if (wid == 0 && lane == 0) {
        asm volatile("mbarrier.inval.shared.b64 [%0];" :: "r"(sbase + SM_MBAR) : "memory");
    }
    __syncthreads();
    if (wid == 0) {
        asm volatile("tcgen05.relinquish_alloc_permit.cta_group::1.sync.aligned;");
        asm volatile("tcgen05.dealloc.cta_group::1.sync.aligned.b32 %0, %1;"
                     :: "r"(tmem), "r"(128u));
    }
#else
    (void)x; (void)W; (void)b; (void)att;
#endif
}

// ---- fallback fp32 SGEMM with fused e_pre (non-sm_103a SASS only) -----------
__global__ __launch_bounds__(256) void k_gemm_fp32(const float* __restrict__ x,
                                                   const float* __restrict__ W,
                                                   const float* __restrict__ b,
                                                   const float* __restrict__ att) {
#if !defined(__CUDA_ARCH_FEAT_SM103_ALL)
    __shared__ float xs[32][132];
    __shared__ float ws[32][132];

    const int tid = threadIdx.x;
    const int tx = tid & 15;
    const int ty = tid >> 4;
    const int row0 = blockIdx.x * 128;

    float acc[8][8];
#pragma unroll
    for (int i = 0; i < 8; i++)
#pragma unroll
        for (int j = 0; j < 8; j++) acc[i][j] = 0.f;

    for (int k0 = 0; k0 < IN_CH; k0 += 32) {
#pragma unroll
        for (int l = 0; l < 4; l++) {
            int idx = tid + l * 256;
            int r  = idx >> 3;
            int kq = idx & 7;
            int grow = row0 + r;
            float4 v = make_float4(0.f, 0.f, 0.f, 0.f);
            if (grow < N_NODES)
                v = *reinterpret_cast<const float4*>(&x[(size_t)grow * IN_CH + k0 + kq * 4]);
            xs[kq * 4 + 0][r] = v.x;
            xs[kq * 4 + 1][r] = v.y;
            xs[kq * 4 + 2][r] = v.z;
            xs[kq * 4 + 3][r] = v.w;
        }
#pragma unroll
        for (int l = 0; l < 4; l++) {
            int idx = tid + l * 256;
            int cc = idx >> 3;
            int kq = idx & 7;
            float4 v = *reinterpret_cast<const float4*>(&W[(size_t)cc * IN_CH + k0 + kq * 4]);
            ws[kq * 4 + 0][cc] = v.x;
            ws[kq * 4 + 1][cc] = v.y;
            ws[kq * 4 + 2][cc] = v.z;
            ws[kq * 4 + 3][cc] = v.w;
        }
        __syncthreads();

#pragma unroll
        for (int kk = 0; kk < 32; kk++) {
            float a[8], bb[8];
            float4 a0 = *reinterpret_cast<const float4*>(&xs[kk][ty * 8]);
            float4 a1 = *reinterpret_cast<const float4*>(&xs[kk][ty * 8 + 4]);
            float4 b0 = *reinterpret_cast<const float4*>(&ws[kk][tx * 8]);
            float4 b1 = *reinterpret_cast<const float4*>(&ws[kk][tx * 8 + 4]);
            a[0]=a0.x; a[1]=a0.y; a[2]=a0.z; a[3]=a0.w;
            a[4]=a1.x; a[5]=a1.y; a[6]=a1.z; a[7]=a1.w;
            bb[0]=b0.x; bb[1]=b0.y; bb[2]=b0.z; bb[3]=b0.w;
            bb[4]=b1.x; bb[5]=b1.y; bb[6]=b1.z; bb[7]=b1.w;
#pragma unroll
            for (int i = 0; i < 8; i++)
#pragma unroll
                for (int j = 0; j < 8; j++)
                    acc[i][j] = fmaf(a[i], bb[j], acc[i][j]);
        }
        __syncthreads();
    }

    // epilogue: write feat
#pragma unroll
    for (int i = 0; i < 8; i++) {
        int grow = row0 + ty * 8 + i;
        if (grow >= N_NODES) break;
#pragma unroll
        for (int j = 0; j < 8; j += 4) {
            int col = tx * 8 + j;
            float4 bv = *reinterpret_cast<const float4*>(&b[col]);
            float4 o;
            o.x = acc[i][j + 0] + bv.x;
            o.y = acc[i][j + 1] + bv.y;
            o.z = acc[i][j + 2] + bv.z;
            o.w = acc[i][j + 3] + bv.w;
            *reinterpret_cast<float4*>(&g_feat[(size_t)grow * HC + col]) = o;
        }
    }

    // fused e_pre: per-thread partial att-dots, reduce over the 16 tx threads
    __syncthreads();
    float* pbuf = &xs[0][0];   // 128 rows * 16 tx * 2 = 4096 floats <= 4224
#pragma unroll
    for (int i = 0; i < 8; i++) {
        int row = ty * 8 + i;
        float s0 = 0.f, s1 = 0.f;
#pragma unroll
        for (int j = 0; j < 8; j++) {
            int col = tx * 8 + j;
            float v = acc[i][j] + b[col];
            s0 = fmaf(v, att[2 * col],     s0);
            s1 = fmaf(v, att[2 * col + 1], s1);
        }
        pbuf[(row * 16 + tx) * 2 + 0] = s0;
        pbuf[(row * 16 + tx) * 2 + 1] = s1;
    }
    __syncthreads();
    if (tid < 128) {
        int grow = row0 + tid;
        if (grow < N_NODES) {
            float t0 = 0.f, t1 = 0.f;
#pragma unroll
            for (int u = 0; u < 16; u++) {
                t0 += pbuf[(tid * 16 + u) * 2 + 0];
                t1 += pbuf[(tid * 16 + u) * 2 + 1];
            }
            g_esrc[grow] = t0;
            g_etar[grow] = t1;
            float z = t0 + t1;
            float lz = z > 0.f ? z : NEG_SLOPE * z;
            g_eself[grow] = expf(lz);
        }
    }
#else
    (void)x; (void)W; (void)b; (void)att;
#endif
}

// ---------------- Kernel 3: histogram (targets only, 4 edges/thread) ---------
__global__ __launch_bounds__(256) void k_hist(const void* __restrict__ ei) {
    int base = (blockIdx.x * blockDim.x + threadIdx.x) * 4;
    if (base >= N_EDGES) return;
    int t[4];
    if (g_is32) {
        int4 v = *reinterpret_cast<const int4*>((const int*)ei + base);
        t[0] = v.x; t[1] = v.y; t[2] = v.z; t[3] = v.w;
    } else {
        const long long* p = (const long long*)ei;
        longlong2 v0 = *reinterpret_cast<const longlong2*>(p + base);
        longlong2 v1 = *reinterpret_cast<const longlong2*>(p + base + 2);
        t[0] = (int)v0.x; t[1] = (int)v0.y; t[2] = (int)v1.x; t[3] = (int)v1.y;
    }
#pragma unroll
    for (int u = 0; u < 4; u++)
        if ((unsigned)t[u] < N_NODES) atomicAdd(&g_counts[t[u]], 1);
}

// ---------------- Kernels 4a/4b/4c: multi-block exclusive scan ---------------
__global__ __launch_bounds__(1024) void k_scan1() {
    __shared__ int wsum[32];
    int i = blockIdx.x * 1024 + threadIdx.x;
    int lane = threadIdx.x & 31, wd = threadIdx.x >> 5;
    int v = (i < N_NODES) ? g_counts[i] : 0;
    int xv = v;
#pragma unroll
    for (int o = 1; o < 32; o <<= 1) {
        int y = __shfl_up_sync(0xffffffffu, xv, o);
        if (lane >= o) xv += y;
    }
    if (lane == 31) wsum[wd] = xv;
    __syncthreads();
    if (wd == 0) {
        int s = wsum[lane];
#pragma unroll
        for (int o = 1; o < 32; o <<= 1) {
            int y = __shfl_up_sync(0xffffffffu, s, o);
            if (lane >= o) s += y;
        }
        wsum[lane] = s;
    }
    __syncthreads();
    int base = (wd > 0) ? wsum[wd - 1] : 0;
    if (i < N_NODES) g_offsets[i] = base + xv - v;
    if (threadIdx.x == 1023) g_bsums[blockIdx.x] = wsum[31];
}

__global__ __launch_bounds__(128) void k_scan2(int nblocks) {
    __shared__ int sh[128];
    int t = threadIdx.x;
    int v = (t < nblocks) ? g_bsums[t] : 0;
    sh[t] = v;
    __syncthreads();
#pragma unroll
    for (int o = 1; o < 128; o <<= 1) {
        int y = (t >= o) ? sh[t - o] : 0;
        __syncthreads();
        sh[t] += y;
        __syncthreads();
    }
    if (t < nblocks) g_bsums[t] = sh[t] - v;
}

__global__ __launch_bounds__(256) void k_scan3() {
    int i = blockIdx.x * blockDim.x + threadIdx.x;
    if (i >= N_NODES) return;
    int off = g_offsets[i] + g_bsums[i >> 10];
    g_offsets[i] = off;
    g_cursor[i]  = off;
}

// ---------------- Kernel 5: scatter (4 edges/thread, PDL primary) ------------
// Single-wave grid (4 blocks/SM, zero smem) so the PDL trigger fires at start
// and leaves room for one GEMM CTA (512 thr + 197KB smem) per SM.
__global__ __launch_bounds__(256) void k_scatter(const void* __restrict__ ei) {
#if __CUDA_ARCH__ >= 900
    cudaTriggerProgrammaticLaunchCompletion();
#endif
    int stride = gridDim.x * blockDim.x * 4;
    for (int base = (blockIdx.x * blockDim.x + threadIdx.x) * 4; base < N_EDGES;
         base += stride) {
        int t[4], s[4];
        if (g_is32) {
            const int* p = (const int*)ei;
            int4 tv = *reinterpret_cast<const int4*>(p + base);
            int4 sv = *reinterpret_cast<const int4*>(p + N_EDGES + base);
            t[0]=tv.x; t[1]=tv.y; t[2]=tv.z; t[3]=tv.w;
            s[0]=sv.x; s[1]=sv.y; s[2]=sv.z; s[3]=sv.w;
        } else {
            const long long* p = (const long long*)ei;
            longlong2 t0 = *reinterpret_cast<const longlong2*>(p + base);
            longlong2 t1 = *reinterpret_cast<const longlong2*>(p + base + 2);
            longlong2 s0 = *reinterpret_cast<const longlong2*>(p + N_EDGES + base);
            longlong2 s1 = *reinterpret_cast<const longlong2*>(p + N_EDGES + base + 2);
            t[0]=(int)t0.x; t[1]=(int)t0.y; t[2]=(int)t1.x; t[3]=(int)t1.y;
            s[0]=(int)s0.x; s[1]=(int)s0.y; s[2]=(int)s1.x; s[3]=(int)s1.y;
        }
#pragma unroll
        for (int u = 0; u < 4; u++) {
            if ((unsigned)t[u] >= N_NODES || (unsigned)s[u] >= N_NODES) continue;
            int pos = atomicAdd(&g_cursor[t[u]], 1);
            g_srcs[pos] = s[u];
        }
    }
}

// ---------------- Kernel 6: aggregation, one warp per node, MLP=8 ------------
__global__ __launch_bounds__(256) void k_agg(float* __restrict__ out) {
    int warp = (blockIdx.x * blockDim.x + threadIdx.x) >> 5;
    if (warp >= N_NODES) return;
    int lane = threadIdx.x & 31;

    const float4* f4 = reinterpret_cast<const float4*>(g_feat);
    int off = g_offsets[warp];
    int cnt = g_counts[warp];
    float etar = g_etar[warp];

    float4 acc = make_float4(0.f, 0.f, 0.f, 0.f);
    float sum_e = 0.f;
    int j = 0;
#pragma unroll 1
    for (; j + 8 <= cnt; j += 8) {
        int sarr[8];
#pragma unroll
        for (int u = 0; u < 8; u++) sarr[u] = g_srcs[off + j + u];
        float earr[8];
#pragma unroll
        for (int u = 0; u < 8; u++) {
            float z = g_esrc[sarr[u]] + etar;
            float lz = z > 0.f ? z : NEG_SLOPE * z;
            earr[u] = expf(lz);
            sum_e += earr[u];
        }
#pragma unroll
        for (int u = 0; u < 8; u++) {
            float4 f = f4[(size_t)sarr[u] * 32 + lane];
            acc.x = fmaf(earr[u], f.x, acc.x);
            acc.y = fmaf(earr[u], f.y, acc.y);
            acc.z = fmaf(earr[u], f.z, acc.z);
            acc.w = fmaf(earr[u], f.w, acc.w);
        }
    }
    for (; j < cnt; j++) {
        int s = g_srcs[off + j];
        float z = g_esrc[s] + etar;
        float lz = z > 0.f ? z : NEG_SLOPE * z;
        float e = expf(lz);
        sum_e += e;
        float4 f = f4[(size_t)s * 32 + lane];
        acc.x = fmaf(e, f.x, acc.x);
        acc.y = fmaf(e, f.y, acc.y);
        acc.z = fmaf(e, f.z, acc.z);
        acc.w = fmaf(e, f.w, acc.w);
    }

    float es  = g_eself[warp];
    float inv = 1.0f / (sum_e + es);
    float4 fs = f4[(size_t)warp * 32 + lane];
    float4 o;
    o.x = (acc.x + es * fs.x) * inv;
    o.y = (acc.y + es * fs.y) * inv;
    o.z = (acc.z + es * fs.z) * inv;
    o.w = (acc.w + es * fs.w) * inv;
    reinterpret_cast<float4*>(out)[(size_t)warp * 32 + lane] = o;
}

// ---------------- launch ------------------------------------------------------
extern "C" void kernel_launch(void* const* d_in, const int* in_sizes, int n_in,
                              void* d_out, int out_size) {
    const float* x   = nullptr;
    const void*  ei  = nullptr;
    const float* W   = nullptr;
    const float* b   = nullptr;
    const float* att = nullptr;
    for (int i = 0; i < n_in; i++) {
        switch (in_sizes[i]) {
            case 25600000: x   = (const float*)d_in[i]; break;
            case 3200000:  ei  = d_in[i];               break;
            case 32768:    W   = (const float*)d_in[i]; break;
            case 128:      b   = (const float*)d_in[i]; break;
            case 256:      att = (const float*)d_in[i]; break;
            default: break;
        }
    }
    float* out = (float*)d_out;
    (void)out_size;

    int scan_blocks = (N_NODES + 1023) / 1024;         // 98
    int gemm_blocks = (N_NODES + 127) / 128;           // 782
    int hist_blocks = (N_EDGES / 4 + 255) / 256;       // 1563

    // CSR chain first (independent of GEMM), then GEMM overlapped with scatter
    // via PDL: scatter triggers at entry, GEMM launch waits only on that.
    k_zero<<<scan_blocks, 1024>>>((const long long*)ei);
    k_hist<<<hist_blocks, 256>>>(ei);
    k_scan1<<<scan_blocks, 1024>>>();
    k_scan2<<<1, 128>>>(scan_blocks);
    k_scan3<<<(N_NODES + 255) / 256, 256>>>();
    k_scatter<<<592, 256>>>(ei);      // single wave (4 blocks/SM), triggers PDL

    cudaFuncSetAttribute(k_gemm_tc5, cudaFuncAttributeMaxDynamicSharedMemorySize, SM_TOTAL);
    {
        cudaLaunchConfig_t cfg = {};
        cfg.gridDim  = dim3(gemm_blocks);
        cfg.blockDim = dim3(512);
        cfg.dynamicSmemBytes = SM_TOTAL;
        cfg.stream = 0;
        cudaLaunchAttribute attrs[1];
        attrs[0].id = cudaLaunchAttributeProgrammaticStreamSerialization;
        attrs[0].val.programmaticStreamSerializationAllowed = 1;
        cfg.attrs = attrs;
        cfg.numAttrs = 1;
        cudaLaunchKernelEx(&cfg, k_gemm_tc5, x, W, b, att);
    }

    k_gemm_fp32<<<gemm_blocks, 256>>>(x, W, b, att);           // no-op on 103a

    int node_warp_blocks = (N_NODES * 32 + 255) / 256;         // 12500
    k_agg<<<node_warp_blocks, 256>>>(out);
}